// round 6
// baseline (speedup 1.0000x reference)
#include <cuda_runtime.h>
#include <math.h>

// Problem constants
#define B_ 4
#define L_ 512
#define M_ 2048
#define D_ 1024
#define H_ 8
#define K_ 128
#define W_ 2560

// -------- scratch (device globals; no allocation allowed) --------
__device__ float g_xt[(size_t)B_ * L_ * D_];
__device__ float g_q [(size_t)B_ * L_ * D_];
__device__ float g_k [(size_t)B_ * L_ * D_];
__device__ float g_v [(size_t)B_ * L_ * D_];
__device__ float g_sin[(size_t)W_ * D_];
__device__ float g_r [(size_t)W_ * D_];
__device__ float g_corr[(size_t)H_ * W_];           // (xl_v - xl_u) . R[row]
__device__ float g_wv[(size_t)B_ * L_ * D_];

// ---------------- helpers ----------------
__device__ __forceinline__ unsigned tf32cvt(float f) {
    unsigned r;
    asm("cvt.rna.tf32.f32 %0, %1;" : "=r"(r) : "f"(f));
    return r;
}
__device__ __forceinline__ void mma8(float* c, const unsigned* a, const unsigned* b) {
    asm("mma.sync.aligned.m16n8k8.row.col.f32.tf32.tf32.f32 "
        "{%0,%1,%2,%3},{%4,%5,%6,%7},{%8,%9},{%0,%1,%2,%3};"
        : "+f"(c[0]), "+f"(c[1]), "+f"(c[2]), "+f"(c[3])
        : "r"(a[0]), "r"(a[1]), "r"(a[2]), "r"(a[3]), "r"(b[0]), "r"(b[1]));
}
__device__ __forceinline__ void cp16(unsigned dst, const void* src) {
    asm volatile("cp.async.cg.shared.global [%0], [%1], 16;" :: "r"(dst), "l"(src));
}
__device__ __forceinline__ void cp_commit() { asm volatile("cp.async.commit_group;"); }
__device__ __forceinline__ void cp_wait1()  { asm volatile("cp.async.wait_group 1;"); }
__device__ __forceinline__ void cp_wait0()  { asm volatile("cp.async.wait_group 0;"); }
__device__ __forceinline__ unsigned saddr(const void* p) {
    return (unsigned)__cvta_generic_to_shared(p);
}

// ---------------- RMSNorm ----------------
__global__ void rmsnorm_kernel(const float* __restrict__ x,
                               const float* __restrict__ g,
                               float* __restrict__ out)
{
    int row = blockIdx.x;
    int tid = threadIdx.x;
    const float4* xr = (const float4*)(x + (size_t)row * D_);
    float4 v = xr[tid];
    float ss = v.x * v.x + v.y * v.y + v.z * v.z + v.w * v.w;
    #pragma unroll
    for (int o = 16; o > 0; o >>= 1) ss += __shfl_xor_sync(0xffffffffu, ss, o);
    __shared__ float ws[8];
    if ((tid & 31) == 0) ws[tid >> 5] = ss;
    __syncthreads();
    if (tid < 8) {
        float t = ws[tid];
        #pragma unroll
        for (int o = 4; o > 0; o >>= 1) t += __shfl_xor_sync(0xffu, t, o);
        if (tid == 0) ws[0] = t;
    }
    __syncthreads();
    float scale = rsqrtf(ws[0] * (1.0f / (float)D_) + 1e-6f);
    float4 gv = ((const float4*)g)[tid];
    float4 o;
    o.x = v.x * scale * gv.x;
    o.y = v.y * scale * gv.y;
    o.z = v.z * scale * gv.z;
    o.w = v.w * scale * gv.w;
    ((float4*)(out + (size_t)row * D_))[tid] = o;
}

// ---------------- sinusoid table ----------------
__global__ void sinusoid_kernel()
{
    __shared__ double fd[512];
    int tid = threadIdx.x;
    int w0 = blockIdx.x * 64;
    for (int i = tid; i < 512; i += 256)
        fd[i] = exp(-(double)i * (9.210340371976184 / 512.0));
    __syncthreads();
    for (int e = tid; e < 64 * 512; e += 256) {
        int w = w0 + (e >> 9);
        int i = e & 511;
        int p = (W_ - 1) - w;
        double ang = (double)p * fd[i];
        double t = ang * 0.15915494309189535;
        t -= floor(t);
        float th = (float)(t * 6.283185307179586);
        float s, c;
        sincosf(th, &s, &c);
        g_sin[(size_t)w * D_ + i]          = s;
        g_sin[(size_t)w * D_ + 512 + i]    = c;
    }
}

// ---------------- corr[h][w] = (xl_v - xl_u) . R[w] ----------------
__global__ void corr_kernel(const float* __restrict__ xlu, const float* __restrict__ xlv)
{
    int w = 448 + blockIdx.x;         // 448..2559
    int hh = threadIdx.x >> 5, lane = threadIdx.x & 31;
    const float4 rv = *(const float4*)(g_r + (size_t)w * D_ + hh * K_ + lane * 4);
    const float4 uv = *(const float4*)(xlu + hh * K_ + lane * 4);
    const float4 vv = *(const float4*)(xlv + hh * K_ + lane * 4);
    float s = (vv.x - uv.x) * rv.x + (vv.y - uv.y) * rv.y
            + (vv.z - uv.z) * rv.z + (vv.w - uv.w) * rv.w;
    #pragma unroll
    for (int o = 16; o > 0; o >>= 1) s += __shfl_xor_sync(0xffffffffu, s, o);
    if (lane == 0) g_corr[(size_t)hh * W_ + w] = s;
}

// ---------------- pipelined 128x128 tf32 GEMM (NN), BK=32 ----------------
#define GEMM_SMEM ((2 * 128 * 36 + 2 * 32 * 132) * 4)
__global__ void __launch_bounds__(256) gemm_nn(
    const float* __restrict__ A,
    const float* __restrict__ B0, const float* __restrict__ B1, const float* __restrict__ B2,
    float* __restrict__ C0, float* __restrict__ C1, float* __restrict__ C2,
    int Nd, int Kd, float a0, float a1, float a2)
{
    const float* Bm; float* C; float alpha;
    if (blockIdx.z == 0)      { Bm = B0; C = C0; alpha = a0; }
    else if (blockIdx.z == 1) { Bm = B1; C = C1; alpha = a1; }
    else                      { Bm = B2; C = C2; alpha = a2; }

    extern __shared__ float smf[];
    float* sA = smf;
    float* sB = smf + 2 * 128 * 36;
    unsigned sAa = saddr(sA), sBa = saddr(sB);

    int tid = threadIdx.x;
    int lane = tid & 31, wid = tid >> 5;
    int wr = wid >> 1, wc = wid & 1;
    int qr = lane >> 2, qc = lane & 3;
    int m0 = blockIdx.y * 128, n0 = blockIdx.x * 128;
    int NIT = Kd >> 5;

    float acc[2][8][4];
    #pragma unroll
    for (int i = 0; i < 2; i++)
        #pragma unroll
        for (int j = 0; j < 8; j++)
            #pragma unroll
            for (int l = 0; l < 4; l++) acc[i][j][l] = 0.f;

    auto load_tiles = [&](int st, int k0) {
        unsigned da = sAa + st * (128 * 36 * 4);
        unsigned db = sBa + st * (32 * 132 * 4);
        #pragma unroll
        for (int j = 0; j < 4; j++) {
            int id = tid + j * 256;
            int ra = id >> 3, ca = (id & 7) << 2;
            cp16(da + (ra * 36 + ca) * 4, A + (size_t)(m0 + ra) * Kd + k0 + ca);
            int rb = id >> 5, cb = (id & 31) << 2;
            cp16(db + (rb * 132 + cb) * 4, Bm + (size_t)(k0 + rb) * Nd + n0 + cb);
        }
    };

    load_tiles(0, 0); cp_commit();

    for (int it = 0; it < NIT; it++) {
        int st = it & 1;
        if (it + 1 < NIT) { load_tiles(st ^ 1, (it + 1) << 5); cp_commit(); cp_wait1(); }
        else cp_wait0();
        __syncthreads();
        const float* cA = sA + st * (128 * 36);
        const float* cB = sB + st * (32 * 132);
        #pragma unroll
        for (int ks = 0; ks < 4; ks++) {
            const int kk = ks * 8;
            unsigned a[2][4], bf[8][2];
            #pragma unroll
            for (int mt = 0; mt < 2; mt++) {
                int r = wr * 32 + mt * 16 + qr;
                a[mt][0] = tf32cvt(cA[r * 36 + kk + qc]);
                a[mt][1] = tf32cvt(cA[(r + 8) * 36 + kk + qc]);
                a[mt][2] = tf32cvt(cA[r * 36 + kk + qc + 4]);
                a[mt][3] = tf32cvt(cA[(r + 8) * 36 + kk + qc + 4]);
            }
            #pragma unroll
            for (int nt = 0; nt < 8; nt++) {
                int cn = wc * 64 + nt * 8 + qr;
                bf[nt][0] = tf32cvt(cB[(kk + qc) * 132 + cn]);
                bf[nt][1] = tf32cvt(cB[(kk + qc + 4) * 132 + cn]);
            }
            #pragma unroll
            for (int mt = 0; mt < 2; mt++)
                #pragma unroll
                for (int nt = 0; nt < 8; nt++)
                    mma8(acc[mt][nt], a[mt], bf[nt]);
        }
        __syncthreads();
    }

    #pragma unroll
    for (int mt = 0; mt < 2; mt++) {
        int r = m0 + wr * 32 + mt * 16 + qr;
        #pragma unroll
        for (int nt = 0; nt < 8; nt++) {
            int col = n0 + wc * 64 + nt * 8 + qc * 2;
            *(float2*)(C + (size_t)r * Nd + col) =
                make_float2(acc[mt][nt][0] * alpha, acc[mt][nt][1] * alpha);
            *(float2*)(C + (size_t)(r + 8) * Nd + col) =
                make_float2(acc[mt][nt][2] * alpha, acc[mt][nt][3] * alpha);
        }
    }
}

// ---------------- fused banded flash attention (bd in-tile), 512 threads ----------------
// smem word layout:
//  Qs(u32)  [64*132] @0       (q/tau + xl_u, tf32)
//  Kf      2x[64*132] @8448   (fp32 -> converted to tf32 bits in place)
//  Vf       [64*136] @25344
//  Rr       [128*132] @34048  ring of R rows (slot = row & 127)
//  Ssm(f32) [64*68]  @50944
//  mrow/lrow/arow @55296
#define ATT_SMEM (55488 * 4)
__global__ void __launch_bounds__(512) attn_fused(
    const float* __restrict__ cacheK, const float* __restrict__ cacheV,
    const float* __restrict__ xlu, const int* __restrict__ posp)
{
    extern __shared__ unsigned smu[];
    unsigned* Qs = smu;
    float* Kf  = (float*)(smu + 8448);
    float* Vf  = (float*)(smu + 25344);
    float* Rr  = (float*)(smu + 34048);
    float* Ssm = (float*)(smu + 50944);
    float* mrow = (float*)(smu + 55296);
    float* lrow = mrow + 64;
    float* arow = lrow + 64;
    unsigned Ka = saddr(Kf), Va = saddr(Vf), Ra = saddr(Rr);

    int tid = threadIdx.x;
    int lane = tid & 31, wid = tid >> 5;       // 16 warps
    int wr = wid >> 2, wc = wid & 3;
    int qr = lane >> 2, qc = lane & 3;
    int bh = blockIdx.y;
    int b = bh >> 3, h = bh & 7;
    int i0 = blockIdx.x * 64;
    int inval = M_ - posp[0]; if (inval < 0) inval = 0;
    const float* rbase = g_r + (size_t)h * K_;
    const float* corrbase = g_corr + (size_t)h * W_;

    auto load_k = [&](int kt, int st) {
        int j0 = i0 + kt * 64;
        unsigned kd = Ka + st * (64 * 132 * 4);
        #pragma unroll
        for (int j = 0; j < 4; j++) {
            int id = tid + j * 512;
            int r2 = id >> 5, c = (id & 31) << 2;
            int jj = j0 + r2;
            const float* kp;
            if (jj < M_) kp = cacheK + ((size_t)bh * M_ + jj) * K_ + c;
            else         kp = g_k + ((size_t)(b * L_ + (jj - M_))) * D_ + h * K_ + c;
            cp16(kd + (r2 * 132 + c) * 4, kp);
        }
    };
    auto load_v = [&](int kt) {
        int j0 = i0 + kt * 64;
        #pragma unroll
        for (int j = 0; j < 4; j++) {
            int id = tid + j * 512;
            int r2 = id >> 5, c = (id & 31) << 2;
            int jj = j0 + r2;
            const float* vp;
            if (jj < M_) vp = cacheV + ((size_t)bh * M_ + jj) * K_ + c;
            else         vp = g_v + ((size_t)(b * L_ + (jj - M_))) * D_ + h * K_ + c;
            cp16(Va + (r2 * 136 + c) * 4, vp);
        }
    };
    auto load_r64 = [&](int wstart) {
        #pragma unroll
        for (int j = 0; j < 4; j++) {
            int id = tid + j * 512;
            int r2 = id >> 5, c = (id & 31) << 2;
            int w = wstart + r2;
            int slot = w & 127;
            int wc2 = w > (W_ - 1) ? (W_ - 1) : w;
            cp16(Ra + (slot * 132 + c) * 4, rbase + (size_t)wc2 * D_ + c);
        }
    };
    // in-place fp32 -> tf32-bits conversion
    auto cvt_region = [&](float* p, int n) {
        for (int i = tid; i < n; i += 512)
            ((unsigned*)p)[i] = tf32cvt(p[i]);
    };

    // ---- prologue: G0 = [K tile0, R rows 448..575] ----
    load_k(0, 0);
    #pragma unroll
    for (int j = 0; j < 8; j++) {    // 128 R rows
        int id = tid + j * 512;
        int r2 = id >> 5, c = (id & 31) << 2;
        int w = 448 + r2;
        cp16(Ra + ((w & 127) * 132 + c) * 4, rbase + (size_t)w * D_ + c);
    }
    cp_commit();

    // Q tile (+ xl_u) -> tf32
    const float* qbase = g_q + ((size_t)(b * L_ + i0)) * D_ + h * K_;
    #pragma unroll
    for (int l = 0; l < 4; l++) {
        int idx = tid + l * 512;
        int r2 = idx >> 5, c = (idx & 31) << 2;
        float4 qv = *(const float4*)(qbase + (size_t)r2 * D_ + c);
        float4 uv = *(const float4*)(xlu + h * K_ + c);
        *(uint4*)&Qs[r2 * 132 + c] = make_uint4(
            tf32cvt(qv.x + uv.x), tf32cvt(qv.y + uv.y),
            tf32cvt(qv.z + uv.z), tf32cvt(qv.w + uv.w));
    }
    if (tid < 64) { mrow[tid] = -1e30f; lrow[tid] = 0.f; }

    float oacc[4][4];
    #pragma unroll
    for (int i = 0; i < 4; i++)
        #pragma unroll
        for (int j = 0; j < 4; j++) oacc[i][j] = 0.f;

    int srow = tid >> 3, sg = tid & 7;          // softmax: 8 lanes/row
    int r = wr * 16 + qr;

    // C-phase band-skip predicate (per n-tile, uniform per warp)
    bool need[4];
    #pragma unroll
    for (int nt = 0; nt < 4; nt++) {
        int T0 = wc * 32 + nt * 8;
        need[nt] = (T0 >= 41 - 16 * wr) && (T0 <= 126 - 16 * wr);
    }

    __syncthreads();

    for (int kt = 0; kt < 33; kt++) {
        int st = kt & 1;
        int j0 = i0 + kt * 64;
        bool hasNext = (kt + 1 < 33);

        // group Ga: V(kt) [+ K(kt+1)]
        load_v(kt);
        if (hasNext) load_k(kt + 1, st ^ 1);
        cp_commit();

        // ensure K(kt) + R window for kt resident (only Ga may be pending)
        cp_wait1();
        __syncthreads();

        // in-place tf32 conversion of freshly-arrived tiles
        cvt_region(Kf + st * (64 * 132), 64 * 132);
        if (kt == 0) cvt_region(Rr, 128 * 132);
        else         cvt_region(Rr + ((kt & 1) ? 64 : 0) * 132, 64 * 132);
        __syncthreads();

        const unsigned* cKu = (const unsigned*)(Kf + st * (64 * 132));
        const unsigned* Ru  = (const unsigned*)Rr;

        // ---- unified mma: S = (Q+u)K^T (16x16/warp) and C = (Q+u)Rwin^T (16x32/warp) ----
        float s[2][4], cf[4][4];
        #pragma unroll
        for (int i = 0; i < 2; i++)
            #pragma unroll
            for (int j = 0; j < 4; j++) s[i][j] = 0.f;
        #pragma unroll
        for (int i = 0; i < 4; i++)
            #pragma unroll
            for (int j = 0; j < 4; j++) cf[i][j] = 0.f;

        int rslot[4];
        #pragma unroll
        for (int nt = 0; nt < 4; nt++) {
            int t = wc * 32 + nt * 8 + qr;
            rslot[nt] = (448 + 64 * kt + t) & 127;
        }

        #pragma unroll
        for (int ks = 0; ks < 16; ks++) {
            const int kk = ks * 8;
            unsigned a[4];
            a[0] = Qs[r * 132 + kk + qc];
            a[1] = Qs[(r + 8) * 132 + kk + qc];
            a[2] = Qs[r * 132 + kk + qc + 4];
            a[3] = Qs[(r + 8) * 132 + kk + qc + 4];
            unsigned bf[2];
            #pragma unroll
            for (int nt = 0; nt < 2; nt++) {
                int n = wc * 16 + nt * 8 + qr;
                bf[0] = cKu[n * 132 + kk + qc];
                bf[1] = cKu[n * 132 + kk + qc + 4];
                mma8(s[nt], a, bf);
            }
            #pragma unroll
            for (int nt = 0; nt < 4; nt++) {
                if (need[nt]) {
                    bf[0] = Ru[rslot[nt] * 132 + kk + qc];
                    bf[1] = Ru[rslot[nt] * 132 + kk + qc + 4];
                    mma8(cf[nt], a, bf);
                }
            }
        }
        // all warps finished reading Rr window before prefetch overwrites it
        __syncthreads();

        // group Gr: prefetch next 64 R rows (overlaps softmax + P@V)
        if (hasNext) { load_r64(576 + 64 * kt); cp_commit(); }

        // ---- scatter bd: Ssm[ri][t-63+ri] = C[ri][t] + corr ----
        #pragma unroll
        for (int nt = 0; nt < 4; nt++) {
            if (!need[nt]) continue;
            int t0 = wc * 32 + nt * 8 + qc * 2;
            #pragma unroll
            for (int e = 0; e < 2; e++) {
                int t = t0 + e;
                int rabs = 448 + 64 * kt + t;
                int ci = rabs > (W_ - 1) ? (W_ - 1) : rabs;
                float cr = corrbase[ci];
                int cj0 = t - 63 + r;
                if (cj0 >= 0 && cj0 < 64) Ssm[r * 68 + cj0] = cf[nt][e] + cr;
                int cj1 = cj0 + 8;
                if (cj1 >= 0 && cj1 < 64) Ssm[(r + 8) * 68 + cj1] = cf[nt][e + 2] + cr;
            }
        }
        __syncthreads();

        // ---- add S + bd + mask ----
        {
            int gi0 = i0 + r, gi1 = gi0 + 8;
            #pragma unroll
            for (int nt = 0; nt < 2; nt++) {
                int cbase = wc * 16 + nt * 8 + qc * 2;
                #pragma unroll
                for (int e = 0; e < 2; e++) {
                    int cc = cbase + e;
                    int gj = j0 + cc;
                    int dd0 = gj - gi0, dd1 = gj - gi1;
                    float b0 = Ssm[r * 68 + cc];
                    float b1 = Ssm[(r + 8) * 68 + cc];
                    float v0 = (dd0 >= 0 && dd0 <= 2048 && gj >= inval) ? (s[nt][e] + b0) : -1e30f;
                    float v1 = (dd1 >= 0 && dd1 <= 2048 && gj >= inval) ? (s[nt][2 + e] + b1) : -1e30f;
                    Ssm[r * 68 + cc] = v0;
                    Ssm[(r + 8) * 68 + cc] = v1;
                }
            }
        }
        __syncthreads();

        // ---- online softmax (8 lanes / row) ----
        {
            float* Sr = Ssm + srow * 68 + sg * 8;
            float mx = -1e30f;
            #pragma unroll
            for (int c2 = 0; c2 < 8; c2++) mx = fmaxf(mx, Sr[c2]);
            mx = fmaxf(mx, __shfl_xor_sync(0xffffffffu, mx, 1));
            mx = fmaxf(mx, __shfl_xor_sync(0xffffffffu, mx, 2));
            mx = fmaxf(mx, __shfl_xor_sync(0xffffffffu, mx, 4));
            float mold = mrow[srow];
            float mnew = fmaxf(mold, mx);
            float sum = 0.f;
            #pragma unroll
            for (int c2 = 0; c2 < 8; c2++) {
                float p = __expf(Sr[c2] - mnew);
                ((unsigned*)Sr)[c2] = tf32cvt(p);
                sum += p;
            }
            sum += __shfl_xor_sync(0xffffffffu, sum, 1);
            sum += __shfl_xor_sync(0xffffffffu, sum, 2);
            sum += __shfl_xor_sync(0xffffffffu, sum, 4);
            if (sg == 0) {
                float alpha = __expf(mold - mnew);
                arow[srow] = alpha;
                lrow[srow] = lrow[srow] * alpha + sum;
                mrow[srow] = mnew;
            }
        }
        // V(kt) must be resident (only Gr may be pending)
        if (hasNext) cp_wait1(); else cp_wait0();
        __syncthreads();

        // in-place convert V to tf32 bits
        cvt_region(Vf, 64 * 136);
        __syncthreads();
        const unsigned* Vu = (const unsigned*)Vf;

        // ---- phase C: rescale + O += P @ V (16x32/warp) ----
        {
            float al0 = arow[r], al1 = arow[r + 8];
            #pragma unroll
            for (int nt = 0; nt < 4; nt++) {
                oacc[nt][0] *= al0; oacc[nt][1] *= al0;
                oacc[nt][2] *= al1; oacc[nt][3] *= al1;
            }
            const unsigned* Pu = (const unsigned*)Ssm;
            #pragma unroll
            for (int ks = 0; ks < 8; ks++) {
                const int kk = ks * 8;
                unsigned a[4], bf[4][2];
                a[0] = Pu[r * 68 + kk + qc];
                a[1] = Pu[(r + 8) * 68 + kk + qc];
                a[2] = Pu[r * 68 + kk + qc + 4];
                a[3] = Pu[(r + 8) * 68 + kk + qc + 4];
                #pragma unroll
                for (int nt = 0; nt < 4; nt++) {
                    int n = wc * 32 + nt * 8 + qr;
                    bf[nt][0] = Vu[(kk + qc) * 136 + n];
                    bf[nt][1] = Vu[(kk + qc + 4) * 136 + n];
                }
                #pragma unroll
                for (int nt = 0; nt < 4; nt++) mma8(oacc[nt], a, bf[nt]);
            }
        }
        __syncthreads();   // protect Vf + Ssm for next iteration
    }

    // epilogue
    {
        float inv0 = 1.0f / lrow[r];
        float inv1 = 1.0f / lrow[r + 8];
        float* o0 = g_wv + ((size_t)(b * L_ + i0 + r)) * D_ + h * K_;
        float* o1 = g_wv + ((size_t)(b * L_ + i0 + r + 8)) * D_ + h * K_;
        #pragma unroll
        for (int nt = 0; nt < 4; nt++) {
            int col = wc * 32 + nt * 8 + qc * 2;
            *(float2*)(o0 + col) = make_float2(oacc[nt][0] * inv0, oacc[nt][1] * inv0);
            *(float2*)(o1 + col) = make_float2(oacc[nt][2] * inv1, oacc[nt][3] * inv1);
        }
    }
}

// ---------------- launch ----------------
extern "C" void kernel_launch(void* const* d_in, const int* in_sizes, int n_in,
                              void* d_out, int out_size)
{
    const float* x      = (const float*)d_in[0];
    const int*   pos    = (const int*)  d_in[1];
    const float* cacheK = (const float*)d_in[2];
    const float* cacheV = (const float*)d_in[3];
    const float* g_rms  = (const float*)d_in[4];
    const float* Wq     = (const float*)d_in[5];
    const float* Wk     = (const float*)d_in[6];
    const float* Wv     = (const float*)d_in[7];
    const float* Wr     = (const float*)d_in[8];
    const float* xlu    = (const float*)d_in[9];
    const float* xlv    = (const float*)d_in[10];
    const float* Wo     = (const float*)d_in[11];
    float* out          = (float*)d_out;

    float *p_xt, *p_q, *p_k, *p_v, *p_sin, *p_r, *p_wv;
    cudaGetSymbolAddress((void**)&p_xt,  g_xt);
    cudaGetSymbolAddress((void**)&p_q,   g_q);
    cudaGetSymbolAddress((void**)&p_k,   g_k);
    cudaGetSymbolAddress((void**)&p_v,   g_v);
    cudaGetSymbolAddress((void**)&p_sin, g_sin);
    cudaGetSymbolAddress((void**)&p_r,   g_r);
    cudaGetSymbolAddress((void**)&p_wv,  g_wv);

    cudaFuncSetAttribute(gemm_nn,    cudaFuncAttributeMaxDynamicSharedMemorySize, GEMM_SMEM);
    cudaFuncSetAttribute(attn_fused, cudaFuncAttributeMaxDynamicSharedMemorySize, ATT_SMEM);

    const float inv_tau = 0.08838834764831845f; // 1/sqrt(128)

    // 1) RMSNorm
    rmsnorm_kernel<<<B_ * L_, 256>>>(x, g_rms, p_xt);

    // 2) fused Q/K/V projections
    gemm_nn<<<dim3(D_ / 128, (B_ * L_) / 128, 3), 256, GEMM_SMEM>>>(
        p_xt, Wq, Wk, Wv, p_q, p_k, p_v, D_, D_, inv_tau, 1.0f, 1.0f);

    // 3) positional keys R = sinusoid @ Wr (rows >= 384)
    sinusoid_kernel<<<W_ / 64, 256>>>();
    gemm_nn<<<dim3(D_ / 128, 17, 1), 256, GEMM_SMEM>>>(
        p_sin + (size_t)384 * D_, Wr, Wr, Wr,
        p_r + (size_t)384 * D_, p_r, p_r, D_, D_, 1.0f, 1.0f, 1.0f);

    // 4) corr vector
    corr_kernel<<<W_ - 448, 256>>>(xlu, xlv);

    // 5) fused banded flash attention (bd in-tile), 512 threads
    attn_fused<<<dim3(L_ / 64, B_ * H_), 512, ATT_SMEM>>>(cacheK, cacheV, xlu, pos);

    // 6) output projection
    gemm_nn<<<dim3(D_ / 128, (B_ * L_) / 128, 1), 256, GEMM_SMEM>>>(
        p_wv, Wo, Wo, Wo, out, out, out, D_, D_, 1.0f, 1.0f, 1.0f);
}

// round 8
// speedup vs baseline: 1.1460x; 1.1460x over previous
#include <cuda_runtime.h>
#include <math.h>

// Problem constants
#define B_ 4
#define L_ 512
#define M_ 2048
#define D_ 1024
#define H_ 8
#define K_ 128
#define W_ 2560

// -------- scratch (device globals; no allocation allowed) --------
__device__ float g_xt[(size_t)B_ * L_ * D_];        // rmsnormed x (tf32-rounded)
__device__ float g_q [(size_t)B_ * L_ * D_];        // q/tau (tf32)
__device__ float g_k [(size_t)B_ * L_ * D_];        // (tf32)
__device__ float g_v [(size_t)B_ * L_ * D_];        // (tf32)
__device__ float g_qu[(size_t)B_ * L_ * D_];        // rnd(q + xl_u)
__device__ float g_qv[(size_t)B_ * L_ * D_];        // rnd(q + xl_v)
__device__ float g_sin[(size_t)W_ * D_];            // (tf32)
__device__ float g_r [(size_t)W_ * D_];             // (tf32)
__device__ float g_bd[(size_t)B_ * H_ * L_ * W_];   // bd[b,h,i,j] absolute-key, fp32
__device__ float g_wv[(size_t)B_ * L_ * D_];        // attn out (tf32)
__device__ float g_ck[(size_t)B_ * H_ * M_ * K_];   // cacheK (tf32)
__device__ float g_cv[(size_t)B_ * H_ * M_ * K_];   // cacheV (tf32)
__device__ float g_wq[(size_t)D_ * D_];             // rounded weights
__device__ float g_wk[(size_t)D_ * D_];
__device__ float g_wvw[(size_t)D_ * D_];
__device__ float g_wr[(size_t)D_ * D_];
__device__ float g_wo[(size_t)D_ * D_];

// ---------------- helpers ----------------
__device__ __forceinline__ unsigned tf32cvt(float f) {
    unsigned r;
    asm("cvt.rna.tf32.f32 %0, %1;" : "=r"(r) : "f"(f));
    return r;
}
__device__ __forceinline__ float tf32rnd(float f) { return __uint_as_float(tf32cvt(f)); }
__device__ __forceinline__ void mma8(float* c, const unsigned* a, const unsigned* b) {
    asm("mma.sync.aligned.m16n8k8.row.col.f32.tf32.tf32.f32 "
        "{%0,%1,%2,%3},{%4,%5,%6,%7},{%8,%9},{%0,%1,%2,%3};"
        : "+f"(c[0]), "+f"(c[1]), "+f"(c[2]), "+f"(c[3])
        : "r"(a[0]), "r"(a[1]), "r"(a[2]), "r"(a[3]), "r"(b[0]), "r"(b[1]));
}
__device__ __forceinline__ void cp16(unsigned dst, const void* src) {
    asm volatile("cp.async.cg.shared.global [%0], [%1], 16;" :: "r"(dst), "l"(src));
}
__device__ __forceinline__ void cp_commit() { asm volatile("cp.async.commit_group;"); }
__device__ __forceinline__ void cp_wait1()  { asm volatile("cp.async.wait_group 1;"); }
__device__ __forceinline__ void cp_wait0()  { asm volatile("cp.async.wait_group 0;"); }
__device__ __forceinline__ unsigned saddr(const void* p) {
    return (unsigned)__cvta_generic_to_shared(p);
}

// ---------------- elementwise tf32 rounding copy ----------------
__global__ void cvt1(float* __restrict__ dst, const float* __restrict__ src, int n4)
{
    int i = blockIdx.x * blockDim.x + threadIdx.x;
    if (i < n4) {
        float4 v = ((const float4*)src)[i];
        ((uint4*)dst)[i] = make_uint4(tf32cvt(v.x), tf32cvt(v.y), tf32cvt(v.z), tf32cvt(v.w));
    }
}

// ---------------- qu/qv = rnd(q + xl_u/v) ----------------
__global__ void quqv_kernel(const float* __restrict__ xlu, const float* __restrict__ xlv)
{
    int row = blockIdx.x;
    int tid = threadIdx.x;
    int h = tid >> 5;
    int off = (tid & 31) * 4;
    size_t base = (size_t)row * D_ + tid * 4;
    float4 q = *(const float4*)(g_q + base);
    float4 u = *(const float4*)(xlu + h * K_ + off);
    float4 v = *(const float4*)(xlv + h * K_ + off);
    *(uint4*)(g_qu + base) = make_uint4(tf32cvt(q.x + u.x), tf32cvt(q.y + u.y),
                                        tf32cvt(q.z + u.z), tf32cvt(q.w + u.w));
    *(uint4*)(g_qv + base) = make_uint4(tf32cvt(q.x + v.x), tf32cvt(q.y + v.y),
                                        tf32cvt(q.z + v.z), tf32cvt(q.w + v.w));
}

// ---------------- RMSNorm (tf32-rounded output) ----------------
__global__ void rmsnorm_kernel(const float* __restrict__ x,
                               const float* __restrict__ g,
                               float* __restrict__ out)
{
    int row = blockIdx.x;
    int tid = threadIdx.x;
    const float4* xr = (const float4*)(x + (size_t)row * D_);
    float4 v = xr[tid];
    float ss = v.x * v.x + v.y * v.y + v.z * v.z + v.w * v.w;
    #pragma unroll
    for (int o = 16; o > 0; o >>= 1) ss += __shfl_xor_sync(0xffffffffu, ss, o);
    __shared__ float ws[8];
    if ((tid & 31) == 0) ws[tid >> 5] = ss;
    __syncthreads();
    if (tid < 8) {
        float t = ws[tid];
        #pragma unroll
        for (int o = 4; o > 0; o >>= 1) t += __shfl_xor_sync(0xffu, t, o);
        if (tid == 0) ws[0] = t;
    }
    __syncthreads();
    float scale = rsqrtf(ws[0] * (1.0f / (float)D_) + 1e-6f);
    float4 gv = ((const float4*)g)[tid];
    *(uint4*)(out + (size_t)row * D_ + tid * 4) = make_uint4(
        tf32cvt(v.x * scale * gv.x), tf32cvt(v.y * scale * gv.y),
        tf32cvt(v.z * scale * gv.z), tf32cvt(v.w * scale * gv.w));
}

// ---------------- sinusoid table (tf32-rounded) ----------------
__global__ void sinusoid_kernel()
{
    __shared__ double fd[512];
    int tid = threadIdx.x;
    int w0 = blockIdx.x * 64;
    for (int i = tid; i < 512; i += 256)
        fd[i] = exp(-(double)i * (9.210340371976184 / 512.0));
    __syncthreads();
    for (int e = tid; e < 64 * 512; e += 256) {
        int w = w0 + (e >> 9);
        int i = e & 511;
        int p = (W_ - 1) - w;
        double ang = (double)p * fd[i];
        double t = ang * 0.15915494309189535;
        t -= floor(t);
        float th = (float)(t * 6.283185307179586);
        float s, c;
        sincosf(th, &s, &c);
        g_sin[(size_t)w * D_ + i]          = tf32rnd(s);
        g_sin[(size_t)w * D_ + 512 + i]    = tf32rnd(c);
    }
}

// ---------------- pipelined 128x128 tf32 GEMM (NN), BK=32, pre-rounded inputs ----------------
#define GEMM_SMEM ((2 * 128 * 36 + 2 * 32 * 132) * 4)
__global__ void __launch_bounds__(256) gemm_nn(
    const float* __restrict__ A,
    const float* __restrict__ B0, const float* __restrict__ B1, const float* __restrict__ B2,
    float* __restrict__ C0, float* __restrict__ C1, float* __restrict__ C2,
    int Nd, int Kd, float a0, float a1, float a2, int rflags)
{
    const float* Bm; float* C; float alpha;
    if (blockIdx.z == 0)      { Bm = B0; C = C0; alpha = a0; }
    else if (blockIdx.z == 1) { Bm = B1; C = C1; alpha = a1; }
    else                      { Bm = B2; C = C2; alpha = a2; }
    bool rnd = (rflags >> blockIdx.z) & 1;

    extern __shared__ float smf[];
    float* sA = smf;
    float* sB = smf + 2 * 128 * 36;
    unsigned sAa = saddr(sA), sBa = saddr(sB);

    int tid = threadIdx.x;
    int lane = tid & 31, wid = tid >> 5;
    int wr = wid >> 1, wc = wid & 1;
    int qr = lane >> 2, qc = lane & 3;
    int m0 = blockIdx.y * 128, n0 = blockIdx.x * 128;
    int NIT = Kd >> 5;

    float acc[2][8][4];
    #pragma unroll
    for (int i = 0; i < 2; i++)
        #pragma unroll
        for (int j = 0; j < 8; j++)
            #pragma unroll
            for (int l = 0; l < 4; l++) acc[i][j][l] = 0.f;

    auto load_tiles = [&](int st, int k0) {
        unsigned da = sAa + st * (128 * 36 * 4);
        unsigned db = sBa + st * (32 * 132 * 4);
        #pragma unroll
        for (int j = 0; j < 4; j++) {
            int id = tid + j * 256;
            int ra = id >> 3, ca = (id & 7) << 2;
            cp16(da + (ra * 36 + ca) * 4, A + (size_t)(m0 + ra) * Kd + k0 + ca);
            int rb = id >> 5, cb = (id & 31) << 2;
            cp16(db + (rb * 132 + cb) * 4, Bm + (size_t)(k0 + rb) * Nd + n0 + cb);
        }
    };

    load_tiles(0, 0); cp_commit();

    for (int it = 0; it < NIT; it++) {
        int st = it & 1;
        if (it + 1 < NIT) { load_tiles(st ^ 1, (it + 1) << 5); cp_commit(); cp_wait1(); }
        else cp_wait0();
        __syncthreads();
        const unsigned* cA = (const unsigned*)(sA + st * (128 * 36));
        const unsigned* cB = (const unsigned*)(sB + st * (32 * 132));
        #pragma unroll
        for (int ks = 0; ks < 4; ks++) {
            const int kk = ks * 8;
            unsigned a[2][4], bf[8][2];
            #pragma unroll
            for (int mt = 0; mt < 2; mt++) {
                int r = wr * 32 + mt * 16 + qr;
                a[mt][0] = cA[r * 36 + kk + qc];
                a[mt][1] = cA[(r + 8) * 36 + kk + qc];
                a[mt][2] = cA[r * 36 + kk + qc + 4];
                a[mt][3] = cA[(r + 8) * 36 + kk + qc + 4];
            }
            #pragma unroll
            for (int nt = 0; nt < 8; nt++) {
                int cn = wc * 64 + nt * 8 + qr;
                bf[nt][0] = cB[(kk + qc) * 132 + cn];
                bf[nt][1] = cB[(kk + qc + 4) * 132 + cn];
            }
            #pragma unroll
            for (int mt = 0; mt < 2; mt++)
                #pragma unroll
                for (int nt = 0; nt < 8; nt++)
                    mma8(acc[mt][nt], a[mt], bf[nt]);
        }
        __syncthreads();
    }

    #pragma unroll
    for (int mt = 0; mt < 2; mt++) {
        int r = m0 + wr * 32 + mt * 16 + qr;
        #pragma unroll
        for (int nt = 0; nt < 8; nt++) {
            int col = n0 + wc * 64 + nt * 8 + qc * 2;
            float v0 = acc[mt][nt][0] * alpha, v1 = acc[mt][nt][1] * alpha;
            float v2 = acc[mt][nt][2] * alpha, v3 = acc[mt][nt][3] * alpha;
            if (rnd) { v0 = tf32rnd(v0); v1 = tf32rnd(v1); v2 = tf32rnd(v2); v3 = tf32rnd(v3); }
            *(float2*)(C + (size_t)r * Nd + col)       = make_float2(v0, v1);
            *(float2*)(C + (size_t)(r + 8) * Nd + col) = make_float2(v2, v3);
        }
    }
}

// ---------------- bd GEMM: bd[bh][i][i+d] = qv_i . R[511+d] ----------------
// grid (17, 4, 32), 256 threads, pipelined BK=32 over K_=128
#define BD_SMEM ((2 * 128 * 36 * 2) * 4)
__global__ void __launch_bounds__(256) bd_mma()
{
    extern __shared__ float smf[];
    float* sA = smf;                      // 2 x [128][36]  (qv rows)
    float* sB = smf + 2 * 128 * 36;       // 2 x [128][36]  (R rows, [n][k])
    unsigned sAa = saddr(sA), sBa = saddr(sB);

    int tid = threadIdx.x;
    int lane = tid & 31, wid = tid >> 5;
    int wr = wid >> 1, wc = wid & 1;
    int qr = lane >> 2, qc = lane & 3;
    int d0 = blockIdx.x * 128;
    int i0 = blockIdx.y * 128;
    int bh = blockIdx.z;
    int b = bh >> 3, h = bh & 7;

    float acc[2][8][4];
    #pragma unroll
    for (int i = 0; i < 2; i++)
        #pragma unroll
        for (int j = 0; j < 8; j++)
            #pragma unroll
            for (int l = 0; l < 4; l++) acc[i][j][l] = 0.f;

    auto load_tiles = [&](int st, int k0) {
        unsigned da = sAa + st * (128 * 36 * 4);
        unsigned db = sBa + st * (128 * 36 * 4);
        #pragma unroll
        for (int j = 0; j < 4; j++) {
            int id = tid + j * 256;
            int r = id >> 3, c = (id & 7) << 2;
            cp16(da + (r * 36 + c) * 4,
                 g_qv + (size_t)(b * L_ + i0 + r) * D_ + h * K_ + k0 + c);
            int rr = 511 + d0 + r; if (rr > W_ - 1) rr = W_ - 1;
            cp16(db + (r * 36 + c) * 4,
                 g_r + (size_t)rr * D_ + h * K_ + k0 + c);
        }
    };

    load_tiles(0, 0); cp_commit();

    for (int it = 0; it < 4; it++) {
        int st = it & 1;
        if (it + 1 < 4) { load_tiles(st ^ 1, (it + 1) << 5); cp_commit(); cp_wait1(); }
        else cp_wait0();
        __syncthreads();
        const unsigned* cA = (const unsigned*)(sA + st * (128 * 36));
        const unsigned* cB = (const unsigned*)(sB + st * (128 * 36));
        #pragma unroll
        for (int ks = 0; ks < 4; ks++) {
            const int kk = ks * 8;
            unsigned a[2][4], bf[8][2];
            #pragma unroll
            for (int mt = 0; mt < 2; mt++) {
                int r = wr * 32 + mt * 16 + qr;
                a[mt][0] = cA[r * 36 + kk + qc];
                a[mt][1] = cA[(r + 8) * 36 + kk + qc];
                a[mt][2] = cA[r * 36 + kk + qc + 4];
                a[mt][3] = cA[(r + 8) * 36 + kk + qc + 4];
            }
            #pragma unroll
            for (int nt = 0; nt < 8; nt++) {
                int cn = wc * 64 + nt * 8 + qr;
                bf[nt][0] = cB[cn * 36 + kk + qc];
                bf[nt][1] = cB[cn * 36 + kk + qc + 4];
            }
            #pragma unroll
            for (int mt = 0; mt < 2; mt++)
                #pragma unroll
                for (int nt = 0; nt < 8; nt++)
                    mma8(acc[mt][nt], a[mt], bf[nt]);
        }
        __syncthreads();
    }

    #pragma unroll
    for (int mt = 0; mt < 2; mt++) {
        int gi = i0 + wr * 32 + mt * 16 + qr;
        float* r0 = g_bd + ((size_t)(bh * L_ + gi)) * W_ + gi;
        float* r1 = g_bd + ((size_t)(bh * L_ + gi + 8)) * W_ + gi + 8;
        #pragma unroll
        for (int nt = 0; nt < 8; nt++) {
            int gd = d0 + wc * 64 + nt * 8 + qc * 2;
            if (gd <= 2048)     { r0[gd]     = acc[mt][nt][0]; r1[gd]     = acc[mt][nt][2]; }
            if (gd + 1 <= 2048) { r0[gd + 1] = acc[mt][nt][1]; r1[gd + 1] = acc[mt][nt][3]; }
        }
    }
}

// ---------------- banded flash attention, pipelined, pre-rounded inputs ----------------
// smem word layout (CORRECTED offsets):
//  Qs(u32)  [64*132]            @0      .. 8448
//  Kf      2x[64*132] = 16896   @8448   .. 25344
//  Vf      2x[64*136] = 17408   @25344  .. 42752
//  Bd      2x[64*68]  = 8704    @42752  .. 51456
//  Ssm      [64*68]   = 4352    @51456  .. 55808
//  mrow/lrow/arow 3*64 = 192    @55808  .. 56000
#define ATT_SMEM (56000 * 4)
__global__ void __launch_bounds__(256) attn_mma(const int* __restrict__ posp)
{
    extern __shared__ unsigned smu[];
    unsigned* Qs = smu;
    float* Kf  = (float*)(smu + 8448);
    float* Vf  = (float*)(smu + 25344);
    float* Bd  = (float*)(smu + 42752);
    float* Ssm = (float*)(smu + 51456);
    float* mrow = (float*)(smu + 55808);
    float* lrow = mrow + 64;
    float* arow = lrow + 64;
    unsigned Ka = saddr(Kf), Va = saddr(Vf), Ba = saddr(Bd);

    int tid = threadIdx.x;
    int lane = tid & 31, wid = tid >> 5;
    int wr = wid >> 1, wc = wid & 1;
    int qr = lane >> 2, qc = lane & 3;
    int bh = blockIdx.y;
    int b = bh >> 3, h = bh & 7;
    int i0 = blockIdx.x * 64;
    int inval = M_ - posp[0]; if (inval < 0) inval = 0;

    auto load_kv = [&](int kt, int st) {
        int j0 = i0 + kt * 64;
        unsigned kd = Ka + st * (64 * 132 * 4);
        unsigned vd = Va + st * (64 * 136 * 4);
        #pragma unroll
        for (int j = 0; j < 8; j++) {
            int id = tid + j * 256;
            int r = id >> 5, c = (id & 31) << 2;
            int jj = j0 + r;
            const float *kp, *vp;
            if (jj < M_) {
                size_t off = ((size_t)bh * M_ + jj) * K_ + c;
                kp = g_ck + off; vp = g_cv + off;
            } else {
                size_t off = ((size_t)(b * L_ + (jj - M_))) * D_ + h * K_ + c;
                kp = g_k + off; vp = g_v + off;
            }
            cp16(kd + (r * 132 + c) * 4, kp);
            cp16(vd + (r * 136 + c) * 4, vp);
        }
        unsigned bd = Ba + st * (64 * 68 * 4);
        const float* bdb = g_bd + ((size_t)(bh * L_ + i0)) * W_ + j0;
        #pragma unroll
        for (int j = 0; j < 4; j++) {
            int id = tid + j * 256;
            int r = id >> 4, c = (id & 15) << 2;
            cp16(bd + (r * 68 + c) * 4, bdb + (size_t)r * W_ + c);
        }
    };

    load_kv(0, 0); cp_commit();

    // Q tile (pre-rounded qu) -> smem, plain copy
    const float* qbase = g_qu + ((size_t)(b * L_ + i0)) * D_ + h * K_;
    #pragma unroll
    for (int l = 0; l < 8; l++) {
        int idx = tid + l * 256;
        int r = idx >> 5, c = (idx & 31) << 2;
        *(uint4*)&Qs[r * 132 + c] = *(const uint4*)(qbase + (size_t)r * D_ + c);
    }
    if (tid < 64) { mrow[tid] = -1e30f; lrow[tid] = 0.f; }

    float oacc[8][4];
    #pragma unroll
    for (int i = 0; i < 8; i++)
        #pragma unroll
        for (int j = 0; j < 4; j++) oacc[i][j] = 0.f;

    int srow = tid >> 2, sg = tid & 3;

    __syncthreads();

    for (int kt = 0; kt < 33; kt++) {
        int st = kt & 1;
        int j0 = i0 + kt * 64;
        if (kt + 1 < 33) { load_kv(kt + 1, st ^ 1); cp_commit(); cp_wait1(); }
        else cp_wait0();
        __syncthreads();

        const unsigned* cK = (const unsigned*)(Kf + st * (64 * 132));
        const unsigned* cV = (const unsigned*)(Vf + st * (64 * 136));
        const float* cB = Bd + st * (64 * 68);

        // phase A: S = (Q+u) K^T
        float s[4][4];
        #pragma unroll
        for (int i = 0; i < 4; i++)
            #pragma unroll
            for (int j = 0; j < 4; j++) s[i][j] = 0.f;
        int r = wr * 16 + qr;
        #pragma unroll
        for (int ks = 0; ks < 16; ks++) {
            const int kk = ks * 8;
            unsigned a[4], bf[4][2];
            a[0] = Qs[r * 132 + kk + qc];
            a[1] = Qs[(r + 8) * 132 + kk + qc];
            a[2] = Qs[r * 132 + kk + qc + 4];
            a[3] = Qs[(r + 8) * 132 + kk + qc + 4];
            #pragma unroll
            for (int nt = 0; nt < 4; nt++) {
                int n = wc * 32 + nt * 8 + qr;
                bf[nt][0] = cK[n * 132 + kk + qc];
                bf[nt][1] = cK[n * 132 + kk + qc + 4];
            }
            #pragma unroll
            for (int nt = 0; nt < 4; nt++) mma8(s[nt], a, bf[nt]);
        }
        // add bd (smem) + mask, write S to smem
        {
            int gi0 = i0 + r, gi1 = gi0 + 8;
            #pragma unroll
            for (int nt = 0; nt < 4; nt++) {
                int cbase = wc * 32 + nt * 8 + qc * 2;
                #pragma unroll
                for (int e = 0; e < 2; e++) {
                    int cc = cbase + e;
                    int gj = j0 + cc;
                    int dd0 = gj - gi0, dd1 = gj - gi1;
                    float b0 = cB[r * 68 + cc];
                    float b1 = cB[(r + 8) * 68 + cc];
                    float v0 = (dd0 >= 0 && dd0 <= 2048 && gj >= inval) ? (s[nt][e] + b0) : -1e30f;
                    float v1 = (dd1 >= 0 && dd1 <= 2048 && gj >= inval) ? (s[nt][2 + e] + b1) : -1e30f;
                    Ssm[r * 68 + cc] = v0;
                    Ssm[(r + 8) * 68 + cc] = v1;
                }
            }
        }
        __syncthreads();

        // online softmax (4 lanes / row); P stored as tf32 bits
        {
            float* Sr = Ssm + srow * 68 + sg * 16;
            float mx = -1e30f;
            #pragma unroll
            for (int c2 = 0; c2 < 16; c2++) mx = fmaxf(mx, Sr[c2]);
            mx = fmaxf(mx, __shfl_xor_sync(0xffffffffu, mx, 1));
            mx = fmaxf(mx, __shfl_xor_sync(0xffffffffu, mx, 2));
            float mold = mrow[srow];
            float mnew = fmaxf(mold, mx);
            float sum = 0.f;
            #pragma unroll
            for (int c2 = 0; c2 < 16; c2++) {
                float p = __expf(Sr[c2] - mnew);
                ((unsigned*)Sr)[c2] = tf32cvt(p);
                sum += p;
            }
            sum += __shfl_xor_sync(0xffffffffu, sum, 1);
            sum += __shfl_xor_sync(0xffffffffu, sum, 2);
            if (sg == 0) {
                float alpha = __expf(mold - mnew);
                arow[srow] = alpha;
                lrow[srow] = lrow[srow] * alpha + sum;
                mrow[srow] = mnew;
            }
        }
        __syncthreads();

        // phase C: rescale + O += P @ V
        {
            int r2 = wr * 16 + qr;
            float al0 = arow[r2], al1 = arow[r2 + 8];
            #pragma unroll
            for (int nt = 0; nt < 8; nt++) {
                oacc[nt][0] *= al0; oacc[nt][1] *= al0;
                oacc[nt][2] *= al1; oacc[nt][3] *= al1;
            }
            const unsigned* Pu = (const unsigned*)Ssm;
            #pragma unroll
            for (int ks = 0; ks < 8; ks++) {
                const int kk = ks * 8;
                unsigned a[4], bf[8][2];
                a[0] = Pu[r2 * 68 + kk + qc];
                a[1] = Pu[(r2 + 8) * 68 + kk + qc];
                a[2] = Pu[r2 * 68 + kk + qc + 4];
                a[3] = Pu[(r2 + 8) * 68 + kk + qc + 4];
                #pragma unroll
                for (int nt = 0; nt < 8; nt++) {
                    int n = wc * 64 + nt * 8 + qr;
                    bf[nt][0] = cV[(kk + qc) * 136 + n];
                    bf[nt][1] = cV[(kk + qc + 4) * 136 + n];
                }
                #pragma unroll
                for (int nt = 0; nt < 8; nt++) mma8(oacc[nt], a, bf[nt]);
            }
        }
        __syncthreads();
    }

    // epilogue: normalize, round to tf32, write wv
    {
        int r = wr * 16 + qr;
        float inv0 = 1.0f / lrow[r];
        float inv1 = 1.0f / lrow[r + 8];
        float* o0 = g_wv + ((size_t)(b * L_ + i0 + r)) * D_ + h * K_;
        float* o1 = g_wv + ((size_t)(b * L_ + i0 + r + 8)) * D_ + h * K_;
        #pragma unroll
        for (int nt = 0; nt < 8; nt++) {
            int col = wc * 64 + nt * 8 + qc * 2;
            *(float2*)(o0 + col) = make_float2(tf32rnd(oacc[nt][0] * inv0), tf32rnd(oacc[nt][1] * inv0));
            *(float2*)(o1 + col) = make_float2(tf32rnd(oacc[nt][2] * inv1), tf32rnd(oacc[nt][3] * inv1));
        }
    }
}

// ---------------- launch ----------------
extern "C" void kernel_launch(void* const* d_in, const int* in_sizes, int n_in,
                              void* d_out, int out_size)
{
    const float* x      = (const float*)d_in[0];
    const int*   pos    = (const int*)  d_in[1];
    const float* cacheK = (const float*)d_in[2];
    const float* cacheV = (const float*)d_in[3];
    const float* g_rms  = (const float*)d_in[4];
    const float* Wq     = (const float*)d_in[5];
    const float* Wk     = (const float*)d_in[6];
    const float* Wv     = (const float*)d_in[7];
    const float* Wr     = (const float*)d_in[8];
    const float* xlu    = (const float*)d_in[9];
    const float* xlv    = (const float*)d_in[10];
    const float* Wo     = (const float*)d_in[11];
    float* out          = (float*)d_out;

    float *p_xt, *p_q, *p_k, *p_v, *p_sin, *p_r, *p_wv;
    float *p_ck, *p_cv, *p_wq, *p_wk, *p_wvw, *p_wr, *p_wo;
    cudaGetSymbolAddress((void**)&p_xt,  g_xt);
    cudaGetSymbolAddress((void**)&p_q,   g_q);
    cudaGetSymbolAddress((void**)&p_k,   g_k);
    cudaGetSymbolAddress((void**)&p_v,   g_v);
    cudaGetSymbolAddress((void**)&p_sin, g_sin);
    cudaGetSymbolAddress((void**)&p_r,   g_r);
    cudaGetSymbolAddress((void**)&p_wv,  g_wv);
    cudaGetSymbolAddress((void**)&p_ck,  g_ck);
    cudaGetSymbolAddress((void**)&p_cv,  g_cv);
    cudaGetSymbolAddress((void**)&p_wq,  g_wq);
    cudaGetSymbolAddress((void**)&p_wk,  g_wk);
    cudaGetSymbolAddress((void**)&p_wvw, g_wvw);
    cudaGetSymbolAddress((void**)&p_wr,  g_wr);
    cudaGetSymbolAddress((void**)&p_wo,  g_wo);

    cudaFuncSetAttribute(gemm_nn,  cudaFuncAttributeMaxDynamicSharedMemorySize, GEMM_SMEM);
    cudaFuncSetAttribute(bd_mma,   cudaFuncAttributeMaxDynamicSharedMemorySize, BD_SMEM);
    cudaFuncSetAttribute(attn_mma, cudaFuncAttributeMaxDynamicSharedMemorySize, ATT_SMEM);

    const float inv_tau = 0.08838834764831845f; // 1/sqrt(128)
    const int NW4 = (D_ * D_) / 4;              // weights, float4 count
    const int NC4 = (B_ * H_ * M_ * K_) / 4;    // caches

    // 0) pre-round weights and caches to tf32
    cvt1<<<NW4 / 256, 256>>>(p_wq,  Wq,  NW4);
    cvt1<<<NW4 / 256, 256>>>(p_wk,  Wk,  NW4);
    cvt1<<<NW4 / 256, 256>>>(p_wvw, Wv,  NW4);
    cvt1<<<NW4 / 256, 256>>>(p_wr,  Wr,  NW4);
    cvt1<<<NW4 / 256, 256>>>(p_wo,  Wo,  NW4);
    cvt1<<<NC4 / 256, 256>>>(p_ck,  cacheK, NC4);
    cvt1<<<NC4 / 256, 256>>>(p_cv,  cacheV, NC4);

    // 1) RMSNorm (tf32 out)
    rmsnorm_kernel<<<B_ * L_, 256>>>(x, g_rms, p_xt);

    // 2) fused Q/K/V projections (outputs rounded)
    gemm_nn<<<dim3(D_ / 128, (B_ * L_) / 128, 3), 256, GEMM_SMEM>>>(
        p_xt, p_wq, p_wk, p_wvw, p_q, p_k, p_v, D_, D_, inv_tau, 1.0f, 1.0f, 0x7);

    // 3) positional keys R = sinusoid @ Wr (rows >= 384), rounded
    sinusoid_kernel<<<W_ / 64, 256>>>();
    gemm_nn<<<dim3(D_ / 128, 17, 1), 256, GEMM_SMEM>>>(
        p_sin + (size_t)384 * D_, p_wr, p_wr, p_wr,
        p_r + (size_t)384 * D_, p_r, p_r, D_, D_, 1.0f, 1.0f, 1.0f, 0x1);

    // 4) qu/qv
    quqv_kernel<<<B_ * L_, 256>>>(xlu, xlv);

    // 5) bd scores
    bd_mma<<<dim3(17, 4, 32), 256, BD_SMEM>>>();

    // 6) banded flash attention
    attn_mma<<<dim3(L_ / 64, B_ * H_), 256, ATT_SMEM>>>(pos);

    // 7) output projection (no rounding)
    gemm_nn<<<dim3(D_ / 128, (B_ * L_) / 128, 1), 256, GEMM_SMEM>>>(
        p_wv, p_wo, p_wo, p_wo, out, out, out, D_, D_, 1.0f, 1.0f, 1.0f, 0x0);
}

// round 9
// speedup vs baseline: 1.2630x; 1.1020x over previous
#include <cuda_runtime.h>
#include <math.h>

// Problem constants
#define B_ 4
#define L_ 512
#define M_ 2048
#define D_ 1024
#define H_ 8
#define K_ 128
#define W_ 2560
#define INV_TAU 0.08838834764831845f

// -------- scratch (device globals; no allocation allowed) --------
__device__ float g_xt[(size_t)B_ * L_ * D_];        // rmsnormed x (tf32-rounded)
__device__ float g_q [(size_t)B_ * L_ * D_];        // q/tau (tf32)
__device__ float g_k [(size_t)B_ * L_ * D_];        // (tf32)
__device__ float g_v [(size_t)B_ * L_ * D_];        // (tf32)
__device__ float g_qu[(size_t)B_ * L_ * D_];        // rnd(q + xl_u)
__device__ float g_qv[(size_t)B_ * L_ * D_];        // rnd(q + xl_v)
__device__ float g_sin[(size_t)W_ * D_];            // (tf32; rows >=384 only)
__device__ float g_r [(size_t)W_ * D_];             // (tf32; rows >=384 only)
__device__ float g_bd[(size_t)B_ * H_ * L_ * W_];   // bd[b,h,i,j] absolute-key, fp32
__device__ float g_wv[(size_t)B_ * L_ * D_];        // attn out (tf32)
__device__ float g_wq[(size_t)D_ * D_];             // rounded weights
__device__ float g_wk[(size_t)D_ * D_];
__device__ float g_wvw[(size_t)D_ * D_];
__device__ float g_wr[(size_t)D_ * D_];
__device__ float g_wo[(size_t)D_ * D_];

// ---------------- helpers ----------------
__device__ __forceinline__ unsigned tf32cvt(float f) {
    unsigned r;
    asm("cvt.rna.tf32.f32 %0, %1;" : "=r"(r) : "f"(f));
    return r;
}
__device__ __forceinline__ float tf32rnd(float f) { return __uint_as_float(tf32cvt(f)); }
__device__ __forceinline__ void mma8(float* c, const unsigned* a, const unsigned* b) {
    asm("mma.sync.aligned.m16n8k8.row.col.f32.tf32.tf32.f32 "
        "{%0,%1,%2,%3},{%4,%5,%6,%7},{%8,%9},{%0,%1,%2,%3};"
        : "+f"(c[0]), "+f"(c[1]), "+f"(c[2]), "+f"(c[3])
        : "r"(a[0]), "r"(a[1]), "r"(a[2]), "r"(a[3]), "r"(b[0]), "r"(b[1]));
}
__device__ __forceinline__ void cp16(unsigned dst, const void* src) {
    asm volatile("cp.async.cg.shared.global [%0], [%1], 16;" :: "r"(dst), "l"(src));
}
__device__ __forceinline__ void cp_commit() { asm volatile("cp.async.commit_group;"); }
__device__ __forceinline__ void cp_wait1()  { asm volatile("cp.async.wait_group 1;"); }
__device__ __forceinline__ void cp_wait0()  { asm volatile("cp.async.wait_group 0;"); }
__device__ __forceinline__ unsigned saddr(const void* p) {
    return (unsigned)__cvta_generic_to_shared(p);
}

// ---------------- elementwise tf32 rounding copy (weights only) ----------------
__global__ void cvt1(float* __restrict__ dst, const float* __restrict__ src, int n4)
{
    int i = blockIdx.x * blockDim.x + threadIdx.x;
    if (i < n4) {
        float4 v = ((const float4*)src)[i];
        ((uint4*)dst)[i] = make_uint4(tf32cvt(v.x), tf32cvt(v.y), tf32cvt(v.z), tf32cvt(v.w));
    }
}

// ---------------- qu/qv = rnd(q + xl_u/v) ----------------
__global__ void quqv_kernel(const float* __restrict__ xlu, const float* __restrict__ xlv)
{
    int row = blockIdx.x;
    int tid = threadIdx.x;
    int h = tid >> 5;
    int off = (tid & 31) * 4;
    size_t base = (size_t)row * D_ + tid * 4;
    float4 q = *(const float4*)(g_q + base);
    float4 u = *(const float4*)(xlu + h * K_ + off);
    float4 v = *(const float4*)(xlv + h * K_ + off);
    *(uint4*)(g_qu + base) = make_uint4(tf32cvt(q.x + u.x), tf32cvt(q.y + u.y),
                                        tf32cvt(q.z + u.z), tf32cvt(q.w + u.w));
    *(uint4*)(g_qv + base) = make_uint4(tf32cvt(q.x + v.x), tf32cvt(q.y + v.y),
                                        tf32cvt(q.z + v.z), tf32cvt(q.w + v.w));
}

// ---------------- RMSNorm (tf32-rounded output) ----------------
__global__ void rmsnorm_kernel(const float* __restrict__ x,
                               const float* __restrict__ g,
                               float* __restrict__ out)
{
    int row = blockIdx.x;
    int tid = threadIdx.x;
    const float4* xr = (const float4*)(x + (size_t)row * D_);
    float4 v = xr[tid];
    float ss = v.x * v.x + v.y * v.y + v.z * v.z + v.w * v.w;
    #pragma unroll
    for (int o = 16; o > 0; o >>= 1) ss += __shfl_xor_sync(0xffffffffu, ss, o);
    __shared__ float ws[8];
    if ((tid & 31) == 0) ws[tid >> 5] = ss;
    __syncthreads();
    if (tid < 8) {
        float t = ws[tid];
        #pragma unroll
        for (int o = 4; o > 0; o >>= 1) t += __shfl_xor_sync(0xffu, t, o);
        if (tid == 0) ws[0] = t;
    }
    __syncthreads();
    float scale = rsqrtf(ws[0] * (1.0f / (float)D_) + 1e-6f);
    float4 gv = ((const float4*)g)[tid];
    *(uint4*)(out + (size_t)row * D_ + tid * 4) = make_uint4(
        tf32cvt(v.x * scale * gv.x), tf32cvt(v.y * scale * gv.y),
        tf32cvt(v.z * scale * gv.z), tf32cvt(v.w * scale * gv.w));
}

// ---------------- sinusoid table (rows >= 384 only, tf32-rounded) ----------------
__global__ void sinusoid_kernel()
{
    __shared__ double fd[512];
    int tid = threadIdx.x;
    int w0 = 384 + blockIdx.x * 64;
    for (int i = tid; i < 512; i += 256)
        fd[i] = exp(-(double)i * (9.210340371976184 / 512.0));
    __syncthreads();
    for (int e = tid; e < 64 * 512; e += 256) {
        int w = w0 + (e >> 9);
        int i = e & 511;
        int p = (W_ - 1) - w;
        double ang = (double)p * fd[i];
        double t = ang * 0.15915494309189535;
        t -= floor(t);
        float th = (float)(t * 6.283185307179586);
        float s, c;
        sincosf(th, &s, &c);
        g_sin[(size_t)w * D_ + i]          = tf32rnd(s);
        g_sin[(size_t)w * D_ + 512 + i]    = tf32rnd(c);
    }
}

// ---------------- fused QKV + R projection GEMM (tf32, pipelined BK=32) ----------------
// grid (8, 17, 4): z=0..2 -> Q/K/V (y<16), z=3 -> R rows 384..2559 (y<17)
#define GEMM_SMEM ((2 * 128 * 36 + 2 * 32 * 132) * 4)
__global__ void __launch_bounds__(256) gemm_qkvr()
{
    const float* A; const float* Bm; float* C; float alpha;
    int z = blockIdx.z;
    if (z == 0)      { A = g_xt; Bm = g_wq;  C = g_q; alpha = INV_TAU; }
    else if (z == 1) { A = g_xt; Bm = g_wk;  C = g_k; alpha = 1.0f; }
    else if (z == 2) { A = g_xt; Bm = g_wvw; C = g_v; alpha = 1.0f; }
    else             { A = g_sin + (size_t)384 * D_; Bm = g_wr;
                       C = g_r + (size_t)384 * D_;  alpha = 1.0f; }
    if (z < 3 && blockIdx.y == 16) return;

    extern __shared__ float smf[];
    float* sA = smf;
    float* sB = smf + 2 * 128 * 36;
    unsigned sAa = saddr(sA), sBa = saddr(sB);

    int tid = threadIdx.x;
    int lane = tid & 31, wid = tid >> 5;
    int wr = wid >> 1, wc = wid & 1;
    int qr = lane >> 2, qc = lane & 3;
    int m0 = blockIdx.y * 128, n0 = blockIdx.x * 128;

    float acc[2][8][4];
    #pragma unroll
    for (int i = 0; i < 2; i++)
        #pragma unroll
        for (int j = 0; j < 8; j++)
            #pragma unroll
            for (int l = 0; l < 4; l++) acc[i][j][l] = 0.f;

    auto load_tiles = [&](int st, int k0) {
        unsigned da = sAa + st * (128 * 36 * 4);
        unsigned db = sBa + st * (32 * 132 * 4);
        #pragma unroll
        for (int j = 0; j < 4; j++) {
            int id = tid + j * 256;
            int ra = id >> 3, ca = (id & 7) << 2;
            cp16(da + (ra * 36 + ca) * 4, A + (size_t)(m0 + ra) * D_ + k0 + ca);
            int rb = id >> 5, cb = (id & 31) << 2;
            cp16(db + (rb * 132 + cb) * 4, Bm + (size_t)(k0 + rb) * D_ + n0 + cb);
        }
    };

    load_tiles(0, 0); cp_commit();

    for (int it = 0; it < 32; it++) {
        int st = it & 1;
        if (it + 1 < 32) { load_tiles(st ^ 1, (it + 1) << 5); cp_commit(); cp_wait1(); }
        else cp_wait0();
        __syncthreads();
        const unsigned* cA = (const unsigned*)(sA + st * (128 * 36));
        const unsigned* cB = (const unsigned*)(sB + st * (32 * 132));
        #pragma unroll
        for (int ks = 0; ks < 4; ks++) {
            const int kk = ks * 8;
            unsigned a[2][4], bf[8][2];
            #pragma unroll
            for (int mt = 0; mt < 2; mt++) {
                int r = wr * 32 + mt * 16 + qr;
                a[mt][0] = cA[r * 36 + kk + qc];
                a[mt][1] = cA[(r + 8) * 36 + kk + qc];
                a[mt][2] = cA[r * 36 + kk + qc + 4];
                a[mt][3] = cA[(r + 8) * 36 + kk + qc + 4];
            }
            #pragma unroll
            for (int nt = 0; nt < 8; nt++) {
                int cn = wc * 64 + nt * 8 + qr;
                bf[nt][0] = cB[(kk + qc) * 132 + cn];
                bf[nt][1] = cB[(kk + qc + 4) * 132 + cn];
            }
            #pragma unroll
            for (int mt = 0; mt < 2; mt++)
                #pragma unroll
                for (int nt = 0; nt < 8; nt++)
                    mma8(acc[mt][nt], a[mt], bf[nt]);
        }
        __syncthreads();
    }

    #pragma unroll
    for (int mt = 0; mt < 2; mt++) {
        int r = m0 + wr * 32 + mt * 16 + qr;
        #pragma unroll
        for (int nt = 0; nt < 8; nt++) {
            int col = n0 + wc * 64 + nt * 8 + qc * 2;
            *(float2*)(C + (size_t)r * D_ + col) =
                make_float2(tf32rnd(acc[mt][nt][0] * alpha), tf32rnd(acc[mt][nt][1] * alpha));
            *(float2*)(C + (size_t)(r + 8) * D_ + col) =
                make_float2(tf32rnd(acc[mt][nt][2] * alpha), tf32rnd(acc[mt][nt][3] * alpha));
        }
    }
}

// ---------------- output projection GEMM (tf32, pipelined BK=32) ----------------
__global__ void __launch_bounds__(256) gemm_out(float* __restrict__ C)
{
    extern __shared__ float smf[];
    float* sA = smf;
    float* sB = smf + 2 * 128 * 36;
    unsigned sAa = saddr(sA), sBa = saddr(sB);

    int tid = threadIdx.x;
    int lane = tid & 31, wid = tid >> 5;
    int wr = wid >> 1, wc = wid & 1;
    int qr = lane >> 2, qc = lane & 3;
    int m0 = blockIdx.y * 128, n0 = blockIdx.x * 128;

    float acc[2][8][4];
    #pragma unroll
    for (int i = 0; i < 2; i++)
        #pragma unroll
        for (int j = 0; j < 8; j++)
            #pragma unroll
            for (int l = 0; l < 4; l++) acc[i][j][l] = 0.f;

    auto load_tiles = [&](int st, int k0) {
        unsigned da = sAa + st * (128 * 36 * 4);
        unsigned db = sBa + st * (32 * 132 * 4);
        #pragma unroll
        for (int j = 0; j < 4; j++) {
            int id = tid + j * 256;
            int ra = id >> 3, ca = (id & 7) << 2;
            cp16(da + (ra * 36 + ca) * 4, g_wv + (size_t)(m0 + ra) * D_ + k0 + ca);
            int rb = id >> 5, cb = (id & 31) << 2;
            cp16(db + (rb * 132 + cb) * 4, g_wo + (size_t)(k0 + rb) * D_ + n0 + cb);
        }
    };

    load_tiles(0, 0); cp_commit();

    for (int it = 0; it < 32; it++) {
        int st = it & 1;
        if (it + 1 < 32) { load_tiles(st ^ 1, (it + 1) << 5); cp_commit(); cp_wait1(); }
        else cp_wait0();
        __syncthreads();
        const unsigned* cA = (const unsigned*)(sA + st * (128 * 36));
        const unsigned* cB = (const unsigned*)(sB + st * (32 * 132));
        #pragma unroll
        for (int ks = 0; ks < 4; ks++) {
            const int kk = ks * 8;
            unsigned a[2][4], bf[8][2];
            #pragma unroll
            for (int mt = 0; mt < 2; mt++) {
                int r = wr * 32 + mt * 16 + qr;
                a[mt][0] = cA[r * 36 + kk + qc];
                a[mt][1] = cA[(r + 8) * 36 + kk + qc];
                a[mt][2] = cA[r * 36 + kk + qc + 4];
                a[mt][3] = cA[(r + 8) * 36 + kk + qc + 4];
            }
            #pragma unroll
            for (int nt = 0; nt < 8; nt++) {
                int cn = wc * 64 + nt * 8 + qr;
                bf[nt][0] = cB[(kk + qc) * 132 + cn];
                bf[nt][1] = cB[(kk + qc + 4) * 132 + cn];
            }
            #pragma unroll
            for (int mt = 0; mt < 2; mt++)
                #pragma unroll
                for (int nt = 0; nt < 8; nt++)
                    mma8(acc[mt][nt], a[mt], bf[nt]);
        }
        __syncthreads();
    }

    #pragma unroll
    for (int mt = 0; mt < 2; mt++) {
        int r = m0 + wr * 32 + mt * 16 + qr;
        #pragma unroll
        for (int nt = 0; nt < 8; nt++) {
            int col = n0 + wc * 64 + nt * 8 + qc * 2;
            *(float2*)(C + (size_t)r * D_ + col)       = make_float2(acc[mt][nt][0], acc[mt][nt][1]);
            *(float2*)(C + (size_t)(r + 8) * D_ + col) = make_float2(acc[mt][nt][2], acc[mt][nt][3]);
        }
    }
}

// ---------------- bd GEMM: bd[bh][i][i+d] = qv_i . R[511+d] ----------------
#define BD_SMEM ((2 * 128 * 36 * 2) * 4)
__global__ void __launch_bounds__(256) bd_mma()
{
    extern __shared__ float smf[];
    float* sA = smf;
    float* sB = smf + 2 * 128 * 36;
    unsigned sAa = saddr(sA), sBa = saddr(sB);

    int tid = threadIdx.x;
    int lane = tid & 31, wid = tid >> 5;
    int wr = wid >> 1, wc = wid & 1;
    int qr = lane >> 2, qc = lane & 3;
    int d0 = blockIdx.x * 128;
    int i0 = blockIdx.y * 128;
    int bh = blockIdx.z;
    int b = bh >> 3, h = bh & 7;

    float acc[2][8][4];
    #pragma unroll
    for (int i = 0; i < 2; i++)
        #pragma unroll
        for (int j = 0; j < 8; j++)
            #pragma unroll
            for (int l = 0; l < 4; l++) acc[i][j][l] = 0.f;

    auto load_tiles = [&](int st, int k0) {
        unsigned da = sAa + st * (128 * 36 * 4);
        unsigned db = sBa + st * (128 * 36 * 4);
        #pragma unroll
        for (int j = 0; j < 4; j++) {
            int id = tid + j * 256;
            int r = id >> 3, c = (id & 7) << 2;
            cp16(da + (r * 36 + c) * 4,
                 g_qv + (size_t)(b * L_ + i0 + r) * D_ + h * K_ + k0 + c);
            int rr = 511 + d0 + r; if (rr > W_ - 1) rr = W_ - 1;
            cp16(db + (r * 36 + c) * 4,
                 g_r + (size_t)rr * D_ + h * K_ + k0 + c);
        }
    };

    load_tiles(0, 0); cp_commit();

    for (int it = 0; it < 4; it++) {
        int st = it & 1;
        if (it + 1 < 4) { load_tiles(st ^ 1, (it + 1) << 5); cp_commit(); cp_wait1(); }
        else cp_wait0();
        __syncthreads();
        const unsigned* cA = (const unsigned*)(sA + st * (128 * 36));
        const unsigned* cB = (const unsigned*)(sB + st * (128 * 36));
        #pragma unroll
        for (int ks = 0; ks < 4; ks++) {
            const int kk = ks * 8;
            unsigned a[2][4], bf[8][2];
            #pragma unroll
            for (int mt = 0; mt < 2; mt++) {
                int r = wr * 32 + mt * 16 + qr;
                a[mt][0] = cA[r * 36 + kk + qc];
                a[mt][1] = cA[(r + 8) * 36 + kk + qc];
                a[mt][2] = cA[r * 36 + kk + qc + 4];
                a[mt][3] = cA[(r + 8) * 36 + kk + qc + 4];
            }
            #pragma unroll
            for (int nt = 0; nt < 8; nt++) {
                int cn = wc * 64 + nt * 8 + qr;
                bf[nt][0] = cB[cn * 36 + kk + qc];
                bf[nt][1] = cB[cn * 36 + kk + qc + 4];
            }
            #pragma unroll
            for (int mt = 0; mt < 2; mt++)
                #pragma unroll
                for (int nt = 0; nt < 8; nt++)
                    mma8(acc[mt][nt], a[mt], bf[nt]);
        }
        __syncthreads();
    }

    #pragma unroll
    for (int mt = 0; mt < 2; mt++) {
        int gi = i0 + wr * 32 + mt * 16 + qr;
        float* r0 = g_bd + ((size_t)(bh * L_ + gi)) * W_ + gi;
        float* r1 = g_bd + ((size_t)(bh * L_ + gi + 8)) * W_ + gi + 8;
        #pragma unroll
        for (int nt = 0; nt < 8; nt++) {
            int gd = d0 + wc * 64 + nt * 8 + qc * 2;
            if (gd <= 2048)     { r0[gd]     = acc[mt][nt][0]; r1[gd]     = acc[mt][nt][2]; }
            if (gd + 1 <= 2048) { r0[gd + 1] = acc[mt][nt][1]; r1[gd + 1] = acc[mt][nt][3]; }
        }
    }
}

// ---------------- banded flash attention, pipelined ----------------
// smem word layout:
//  Qs(u32)  [64*132]            @0      .. 8448
//  Kf(f32) 2x[64*132] = 16896   @8448   .. 25344
//  Vf(f32) 2x[64*136] = 17408   @25344  .. 42752
//  Bd(f32) 2x[64*68]  = 8704    @42752  .. 51456
//  Ssm(f32) [64*68]   = 4352    @51456  .. 55808
//  mrow/lrow/arow 3*64 = 192    @55808  .. 56000
#define ATT_SMEM (56000 * 4)
__global__ void __launch_bounds__(256) attn_mma(
    const float* __restrict__ cacheK, const float* __restrict__ cacheV,
    const int* __restrict__ posp)
{
    extern __shared__ unsigned smu[];
    unsigned* Qs = smu;
    float* Kf  = (float*)(smu + 8448);
    float* Vf  = (float*)(smu + 25344);
    float* Bd  = (float*)(smu + 42752);
    float* Ssm = (float*)(smu + 51456);
    float* mrow = (float*)(smu + 55808);
    float* lrow = mrow + 64;
    float* arow = lrow + 64;
    unsigned Ka = saddr(Kf), Va = saddr(Vf), Ba = saddr(Bd);

    int tid = threadIdx.x;
    int lane = tid & 31, wid = tid >> 5;
    int wr = wid >> 1, wc = wid & 1;
    int qr = lane >> 2, qc = lane & 3;
    int bh = blockIdx.y;
    int b = bh >> 3, h = bh & 7;
    int i0 = blockIdx.x * 64;
    int inval = M_ - posp[0]; if (inval < 0) inval = 0;

    auto load_kv = [&](int kt, int st) {
        int j0 = i0 + kt * 64;
        unsigned kd = Ka + st * (64 * 132 * 4);
        unsigned vd = Va + st * (64 * 136 * 4);
        #pragma unroll
        for (int j = 0; j < 8; j++) {
            int id = tid + j * 256;
            int r = id >> 5, c = (id & 31) << 2;
            int jj = j0 + r;
            const float *kp, *vp;
            if (jj < M_) {
                size_t off = ((size_t)bh * M_ + jj) * K_ + c;
                kp = cacheK + off; vp = cacheV + off;
            } else {
                size_t off = ((size_t)(b * L_ + (jj - M_))) * D_ + h * K_ + c;
                kp = g_k + off; vp = g_v + off;
            }
            cp16(kd + (r * 132 + c) * 4, kp);
            cp16(vd + (r * 136 + c) * 4, vp);
        }
        unsigned bd = Ba + st * (64 * 68 * 4);
        const float* bdb = g_bd + ((size_t)(bh * L_ + i0)) * W_ + j0;
        #pragma unroll
        for (int j = 0; j < 4; j++) {
            int id = tid + j * 256;
            int r = id >> 4, c = (id & 15) << 2;
            cp16(bd + (r * 68 + c) * 4, bdb + (size_t)r * W_ + c);
        }
    };

    load_kv(0, 0); cp_commit();

    // Q tile (pre-rounded qu) -> smem, plain copy
    const float* qbase = g_qu + ((size_t)(b * L_ + i0)) * D_ + h * K_;
    #pragma unroll
    for (int l = 0; l < 8; l++) {
        int idx = tid + l * 256;
        int r = idx >> 5, c = (idx & 31) << 2;
        *(uint4*)&Qs[r * 132 + c] = *(const uint4*)(qbase + (size_t)r * D_ + c);
    }
    if (tid < 64) { mrow[tid] = -1e30f; lrow[tid] = 0.f; }

    float oacc[8][4];
    #pragma unroll
    for (int i = 0; i < 8; i++)
        #pragma unroll
        for (int j = 0; j < 4; j++) oacc[i][j] = 0.f;

    int srow = tid >> 2, sg = tid & 3;

    __syncthreads();

    for (int kt = 0; kt < 33; kt++) {
        int st = kt & 1;
        int j0 = i0 + kt * 64;
        if (kt + 1 < 33) { load_kv(kt + 1, st ^ 1); cp_commit(); cp_wait1(); }
        else cp_wait0();
        __syncthreads();

        const float* cKf = Kf + st * (64 * 132);
        const float* cVf = Vf + st * (64 * 136);
        const float* cB = Bd + st * (64 * 68);

        // phase A: S = (Q+u) K^T   (K converted at fragment load)
        float s[4][4];
        #pragma unroll
        for (int i = 0; i < 4; i++)
            #pragma unroll
            for (int j = 0; j < 4; j++) s[i][j] = 0.f;
        int r = wr * 16 + qr;
        #pragma unroll
        for (int ks = 0; ks < 16; ks++) {
            const int kk = ks * 8;
            unsigned a[4], bf[4][2];
            a[0] = Qs[r * 132 + kk + qc];
            a[1] = Qs[(r + 8) * 132 + kk + qc];
            a[2] = Qs[r * 132 + kk + qc + 4];
            a[3] = Qs[(r + 8) * 132 + kk + qc + 4];
            #pragma unroll
            for (int nt = 0; nt < 4; nt++) {
                int n = wc * 32 + nt * 8 + qr;
                bf[nt][0] = tf32cvt(cKf[n * 132 + kk + qc]);
                bf[nt][1] = tf32cvt(cKf[n * 132 + kk + qc + 4]);
            }
            #pragma unroll
            for (int nt = 0; nt < 4; nt++) mma8(s[nt], a, bf[nt]);
        }
        // add bd (smem) + mask, write S to smem
        {
            int gi0 = i0 + r, gi1 = gi0 + 8;
            #pragma unroll
            for (int nt = 0; nt < 4; nt++) {
                int cbase = wc * 32 + nt * 8 + qc * 2;
                #pragma unroll
                for (int e = 0; e < 2; e++) {
                    int cc = cbase + e;
                    int gj = j0 + cc;
                    int dd0 = gj - gi0, dd1 = gj - gi1;
                    float b0 = cB[r * 68 + cc];
                    float b1 = cB[(r + 8) * 68 + cc];
                    float v0 = (dd0 >= 0 && dd0 <= 2048 && gj >= inval) ? (s[nt][e] + b0) : -1e30f;
                    float v1 = (dd1 >= 0 && dd1 <= 2048 && gj >= inval) ? (s[nt][2 + e] + b1) : -1e30f;
                    Ssm[r * 68 + cc] = v0;
                    Ssm[(r + 8) * 68 + cc] = v1;
                }
            }
        }
        __syncthreads();

        // online softmax (4 lanes / row); P stored as tf32 bits
        {
            float* Sr = Ssm + srow * 68 + sg * 16;
            float mx = -1e30f;
            #pragma unroll
            for (int c2 = 0; c2 < 16; c2++) mx = fmaxf(mx, Sr[c2]);
            mx = fmaxf(mx, __shfl_xor_sync(0xffffffffu, mx, 1));
            mx = fmaxf(mx, __shfl_xor_sync(0xffffffffu, mx, 2));
            float mold = mrow[srow];
            float mnew = fmaxf(mold, mx);
            float sum = 0.f;
            #pragma unroll
            for (int c2 = 0; c2 < 16; c2++) {
                float p = __expf(Sr[c2] - mnew);
                ((unsigned*)Sr)[c2] = tf32cvt(p);
                sum += p;
            }
            sum += __shfl_xor_sync(0xffffffffu, sum, 1);
            sum += __shfl_xor_sync(0xffffffffu, sum, 2);
            if (sg == 0) {
                float alpha = __expf(mold - mnew);
                arow[srow] = alpha;
                lrow[srow] = lrow[srow] * alpha + sum;
                mrow[srow] = mnew;
            }
        }
        __syncthreads();

        // phase C: rescale + O += P @ V   (V converted at fragment load)
        {
            int r2 = wr * 16 + qr;
            float al0 = arow[r2], al1 = arow[r2 + 8];
            #pragma unroll
            for (int nt = 0; nt < 8; nt++) {
                oacc[nt][0] *= al0; oacc[nt][1] *= al0;
                oacc[nt][2] *= al1; oacc[nt][3] *= al1;
            }
            const unsigned* Pu = (const unsigned*)Ssm;
            #pragma unroll
            for (int ks = 0; ks < 8; ks++) {
                const int kk = ks * 8;
                unsigned a[4], bf[8][2];
                a[0] = Pu[r2 * 68 + kk + qc];
                a[1] = Pu[(r2 + 8) * 68 + kk + qc];
                a[2] = Pu[r2 * 68 + kk + qc + 4];
                a[3] = Pu[(r2 + 8) * 68 + kk + qc + 4];
                #pragma unroll
                for (int nt = 0; nt < 8; nt++) {
                    int n = wc * 64 + nt * 8 + qr;
                    bf[nt][0] = tf32cvt(cVf[(kk + qc) * 136 + n]);
                    bf[nt][1] = tf32cvt(cVf[(kk + qc + 4) * 136 + n]);
                }
                #pragma unroll
                for (int nt = 0; nt < 8; nt++) mma8(oacc[nt], a, bf[nt]);
            }
        }
        __syncthreads();
    }

    // epilogue: normalize, round to tf32, write wv
    {
        int r = wr * 16 + qr;
        float inv0 = 1.0f / lrow[r];
        float inv1 = 1.0f / lrow[r + 8];
        float* o0 = g_wv + ((size_t)(b * L_ + i0 + r)) * D_ + h * K_;
        float* o1 = g_wv + ((size_t)(b * L_ + i0 + r + 8)) * D_ + h * K_;
        #pragma unroll
        for (int nt = 0; nt < 8; nt++) {
            int col = wc * 64 + nt * 8 + qc * 2;
            *(float2*)(o0 + col) = make_float2(tf32rnd(oacc[nt][0] * inv0), tf32rnd(oacc[nt][1] * inv0));
            *(float2*)(o1 + col) = make_float2(tf32rnd(oacc[nt][2] * inv1), tf32rnd(oacc[nt][3] * inv1));
        }
    }
}

// ---------------- launch ----------------
extern "C" void kernel_launch(void* const* d_in, const int* in_sizes, int n_in,
                              void* d_out, int out_size)
{
    const float* x      = (const float*)d_in[0];
    const int*   pos    = (const int*)  d_in[1];
    const float* cacheK = (const float*)d_in[2];
    const float* cacheV = (const float*)d_in[3];
    const float* g_rms  = (const float*)d_in[4];
    const float* Wq     = (const float*)d_in[5];
    const float* Wk     = (const float*)d_in[6];
    const float* Wv     = (const float*)d_in[7];
    const float* Wr     = (const float*)d_in[8];
    const float* xlu    = (const float*)d_in[9];
    const float* xlv    = (const float*)d_in[10];
    const float* Wo     = (const float*)d_in[11];
    float* out          = (float*)d_out;

    float *p_xt, *p_wq, *p_wk, *p_wvw, *p_wr, *p_wo;
    cudaGetSymbolAddress((void**)&p_xt,  g_xt);
    cudaGetSymbolAddress((void**)&p_wq,  g_wq);
    cudaGetSymbolAddress((void**)&p_wk,  g_wk);
    cudaGetSymbolAddress((void**)&p_wvw, g_wvw);
    cudaGetSymbolAddress((void**)&p_wr,  g_wr);
    cudaGetSymbolAddress((void**)&p_wo,  g_wo);

    cudaFuncSetAttribute(gemm_qkvr, cudaFuncAttributeMaxDynamicSharedMemorySize, GEMM_SMEM);
    cudaFuncSetAttribute(gemm_out,  cudaFuncAttributeMaxDynamicSharedMemorySize, GEMM_SMEM);
    cudaFuncSetAttribute(bd_mma,    cudaFuncAttributeMaxDynamicSharedMemorySize, BD_SMEM);
    cudaFuncSetAttribute(attn_mma,  cudaFuncAttributeMaxDynamicSharedMemorySize, ATT_SMEM);

    const int NW4 = (D_ * D_) / 4;

    // 0) pre-round weights to tf32 (cheap; caches are NOT copied)
    cvt1<<<NW4 / 256, 256>>>(p_wq,  Wq,  NW4);
    cvt1<<<NW4 / 256, 256>>>(p_wk,  Wk,  NW4);
    cvt1<<<NW4 / 256, 256>>>(p_wvw, Wv,  NW4);
    cvt1<<<NW4 / 256, 256>>>(p_wr,  Wr,  NW4);
    cvt1<<<NW4 / 256, 256>>>(p_wo,  Wo,  NW4);

    // 1) RMSNorm (tf32 out) + sinusoid rows >= 384
    rmsnorm_kernel<<<B_ * L_, 256>>>(x, g_rms, p_xt);
    sinusoid_kernel<<<(W_ - 384) / 64, 256>>>();

    // 2) fused Q/K/V + R projections
    gemm_qkvr<<<dim3(D_ / 128, 17, 4), 256, GEMM_SMEM>>>();

    // 3) qu/qv
    quqv_kernel<<<B_ * L_, 256>>>(xlu, xlv);

    // 4) bd scores
    bd_mma<<<dim3(17, 4, 32), 256, BD_SMEM>>>();

    // 5) banded flash attention
    attn_mma<<<dim3(L_ / 64, B_ * H_), 256, ATT_SMEM>>>(cacheK, cacheV, pos);

    // 6) output projection
    gemm_out<<<dim3(D_ / 128, (B_ * L_) / 128), 256, GEMM_SMEM>>>(out);
}

// round 10
// speedup vs baseline: 1.2680x; 1.0040x over previous
#include <cuda_runtime.h>
#include <math.h>

// Problem constants
#define B_ 4
#define L_ 512
#define M_ 2048
#define D_ 1024
#define H_ 8
#define K_ 128
#define W_ 2560
#define INV_TAU 0.08838834764831845f

// -------- scratch (device globals; no allocation allowed) --------
__device__ float g_xt[(size_t)B_ * L_ * D_];        // rmsnormed x (tf32-rounded)
__device__ float g_k [(size_t)B_ * L_ * D_];        // (tf32)
__device__ float g_v [(size_t)B_ * L_ * D_];        // (tf32)
__device__ float g_qu[(size_t)B_ * L_ * D_];        // rnd(q/tau + xl_u)
__device__ float g_qv[(size_t)B_ * L_ * D_];        // rnd(q/tau + xl_v)
__device__ float g_sin[(size_t)W_ * D_];            // (tf32; rows >=384 only)
__device__ float g_r [(size_t)W_ * D_];             // (tf32; rows >=384 only)
__device__ float g_bd[(size_t)B_ * H_ * L_ * W_];   // bd[b,h,i,j] absolute-key, fp32
__device__ float g_wv[(size_t)B_ * L_ * D_];        // attn out (tf32)
__device__ float g_wq[(size_t)D_ * D_];             // rounded weights
__device__ float g_wk[(size_t)D_ * D_];
__device__ float g_wvw[(size_t)D_ * D_];
__device__ float g_wr[(size_t)D_ * D_];
__device__ float g_wo[(size_t)D_ * D_];

// ---------------- helpers ----------------
__device__ __forceinline__ unsigned tf32cvt(float f) {
    unsigned r;
    asm("cvt.rna.tf32.f32 %0, %1;" : "=r"(r) : "f"(f));
    return r;
}
__device__ __forceinline__ float tf32rnd(float f) { return __uint_as_float(tf32cvt(f)); }
__device__ __forceinline__ void mma8(float* c, const unsigned* a, const unsigned* b) {
    asm("mma.sync.aligned.m16n8k8.row.col.f32.tf32.tf32.f32 "
        "{%0,%1,%2,%3},{%4,%5,%6,%7},{%8,%9},{%0,%1,%2,%3};"
        : "+f"(c[0]), "+f"(c[1]), "+f"(c[2]), "+f"(c[3])
        : "r"(a[0]), "r"(a[1]), "r"(a[2]), "r"(a[3]), "r"(b[0]), "r"(b[1]));
}
__device__ __forceinline__ void cp16(unsigned dst, const void* src) {
    asm volatile("cp.async.cg.shared.global [%0], [%1], 16;" :: "r"(dst), "l"(src));
}
__device__ __forceinline__ void cp_commit() { asm volatile("cp.async.commit_group;"); }
__device__ __forceinline__ void cp_wait1()  { asm volatile("cp.async.wait_group 1;"); }
__device__ __forceinline__ void cp_wait0()  { asm volatile("cp.async.wait_group 0;"); }
__device__ __forceinline__ unsigned saddr(const void* p) {
    return (unsigned)__cvta_generic_to_shared(p);
}

// ---------------- fused weight tf32 rounding copy ----------------
__global__ void cvt5(const float* __restrict__ wq, const float* __restrict__ wk,
                     const float* __restrict__ wv, const float* __restrict__ wr,
                     const float* __restrict__ wo)
{
    const float* src; float* dst;
    switch (blockIdx.y) {
        case 0: src = wq; dst = g_wq;  break;
        case 1: src = wk; dst = g_wk;  break;
        case 2: src = wv; dst = g_wvw; break;
        case 3: src = wr; dst = g_wr;  break;
        default: src = wo; dst = g_wo; break;
    }
    int i = blockIdx.x * blockDim.x + threadIdx.x;
    float4 v = ((const float4*)src)[i];
    ((uint4*)dst)[i] = make_uint4(tf32cvt(v.x), tf32cvt(v.y), tf32cvt(v.z), tf32cvt(v.w));
}

// ---------------- RMSNorm (tf32-rounded output) ----------------
__global__ void rmsnorm_kernel(const float* __restrict__ x,
                               const float* __restrict__ g,
                               float* __restrict__ out)
{
    int row = blockIdx.x;
    int tid = threadIdx.x;
    const float4* xr = (const float4*)(x + (size_t)row * D_);
    float4 v = xr[tid];
    float ss = v.x * v.x + v.y * v.y + v.z * v.z + v.w * v.w;
    #pragma unroll
    for (int o = 16; o > 0; o >>= 1) ss += __shfl_xor_sync(0xffffffffu, ss, o);
    __shared__ float ws[8];
    if ((tid & 31) == 0) ws[tid >> 5] = ss;
    __syncthreads();
    if (tid < 8) {
        float t = ws[tid];
        #pragma unroll
        for (int o = 4; o > 0; o >>= 1) t += __shfl_xor_sync(0xffu, t, o);
        if (tid == 0) ws[0] = t;
    }
    __syncthreads();
    float scale = rsqrtf(ws[0] * (1.0f / (float)D_) + 1e-6f);
    float4 gv = ((const float4*)g)[tid];
    *(uint4*)(out + (size_t)row * D_ + tid * 4) = make_uint4(
        tf32cvt(v.x * scale * gv.x), tf32cvt(v.y * scale * gv.y),
        tf32cvt(v.z * scale * gv.z), tf32cvt(v.w * scale * gv.w));
}

// ---------------- sinusoid table (rows >= 384 only, tf32-rounded) ----------------
__global__ void sinusoid_kernel()
{
    __shared__ double fd[512];
    int tid = threadIdx.x;
    int w0 = 384 + blockIdx.x * 64;
    for (int i = tid; i < 512; i += 256)
        fd[i] = exp(-(double)i * (9.210340371976184 / 512.0));
    __syncthreads();
    for (int e = tid; e < 64 * 512; e += 256) {
        int w = w0 + (e >> 9);
        int i = e & 511;
        int p = (W_ - 1) - w;
        double ang = (double)p * fd[i];
        double t = ang * 0.15915494309189535;
        t -= floor(t);
        float th = (float)(t * 6.283185307179586);
        float s, c;
        sincosf(th, &s, &c);
        g_sin[(size_t)w * D_ + i]          = tf32rnd(s);
        g_sin[(size_t)w * D_ + 512 + i]    = tf32rnd(c);
    }
}

// ---------------- fused QKV + R projection GEMM (tf32, 3-stage BK=32) ----------------
// grid (8, 17, 4): z=0 -> Q (emits qu/qv), z=1 K, z=2 V (y<16), z=3 R rows 384..2559
#define GEMM_SMEM (3 * (128 * 36 + 32 * 132) * 4)
__global__ void __launch_bounds__(256) gemm_qkvr(const float* __restrict__ xlu,
                                                 const float* __restrict__ xlv)
{
    const float* A; const float* Bm;
    int z = blockIdx.z;
    if (z == 0)      { A = g_xt; Bm = g_wq;  }
    else if (z == 1) { A = g_xt; Bm = g_wk;  }
    else if (z == 2) { A = g_xt; Bm = g_wvw; }
    else             { A = g_sin + (size_t)384 * D_; Bm = g_wr; }
    if (z < 3 && blockIdx.y == 16) return;

    extern __shared__ float smf[];
    float* sA = smf;                        // 3 x [128][36]
    float* sB = smf + 3 * 128 * 36;         // 3 x [32][132]
    unsigned sAa = saddr(sA), sBa = saddr(sB);

    int tid = threadIdx.x;
    int lane = tid & 31, wid = tid >> 5;
    int wr = wid >> 1, wc = wid & 1;
    int qr = lane >> 2, qc = lane & 3;
    int m0 = blockIdx.y * 128, n0 = blockIdx.x * 128;

    float acc[2][8][4];
    #pragma unroll
    for (int i = 0; i < 2; i++)
        #pragma unroll
        for (int j = 0; j < 8; j++)
            #pragma unroll
            for (int l = 0; l < 4; l++) acc[i][j][l] = 0.f;

    auto load_tiles = [&](int st, int k0) {
        unsigned da = sAa + st * (128 * 36 * 4);
        unsigned db = sBa + st * (32 * 132 * 4);
        #pragma unroll
        for (int j = 0; j < 4; j++) {
            int id = tid + j * 256;
            int ra = id >> 3, ca = (id & 7) << 2;
            cp16(da + (ra * 36 + ca) * 4, A + (size_t)(m0 + ra) * D_ + k0 + ca);
            int rb = id >> 5, cb = (id & 31) << 2;
            cp16(db + (rb * 132 + cb) * 4, Bm + (size_t)(k0 + rb) * D_ + n0 + cb);
        }
    };

    load_tiles(0, 0);  cp_commit();
    load_tiles(1, 32); cp_commit();

    for (int it = 0; it < 32; it++) {
        int st = it % 3;
        if (it < 30) cp_wait1(); else cp_wait0();
        __syncthreads();
        if (it + 2 < 32) { load_tiles((it + 2) % 3, (it + 2) << 5); cp_commit(); }

        const unsigned* cA = (const unsigned*)(sA + st * (128 * 36));
        const unsigned* cB = (const unsigned*)(sB + st * (32 * 132));
        #pragma unroll
        for (int ks = 0; ks < 4; ks++) {
            const int kk = ks * 8;
            unsigned a[2][4], bf[8][2];
            #pragma unroll
            for (int mt = 0; mt < 2; mt++) {
                int r = wr * 32 + mt * 16 + qr;
                a[mt][0] = cA[r * 36 + kk + qc];
                a[mt][1] = cA[(r + 8) * 36 + kk + qc];
                a[mt][2] = cA[r * 36 + kk + qc + 4];
                a[mt][3] = cA[(r + 8) * 36 + kk + qc + 4];
            }
            #pragma unroll
            for (int nt = 0; nt < 8; nt++) {
                int cn = wc * 64 + nt * 8 + qr;
                bf[nt][0] = cB[(kk + qc) * 132 + cn];
                bf[nt][1] = cB[(kk + qc + 4) * 132 + cn];
            }
            #pragma unroll
            for (int mt = 0; mt < 2; mt++)
                #pragma unroll
                for (int nt = 0; nt < 8; nt++)
                    mma8(acc[mt][nt], a[mt], bf[nt]);
        }
    }

    // epilogue
    if (z == 0) {
        // q = acc * inv_tau;  qu = rnd(q + xlu[col]); qv = rnd(q + xlv[col])
        #pragma unroll
        for (int mt = 0; mt < 2; mt++) {
            int r = m0 + wr * 32 + mt * 16 + qr;
            #pragma unroll
            for (int nt = 0; nt < 8; nt++) {
                int col = n0 + wc * 64 + nt * 8 + qc * 2;
                float q0 = acc[mt][nt][0] * INV_TAU, q1 = acc[mt][nt][1] * INV_TAU;
                float q2 = acc[mt][nt][2] * INV_TAU, q3 = acc[mt][nt][3] * INV_TAU;
                float u0 = xlu[col], u1 = xlu[col + 1];
                float v0 = xlv[col], v1 = xlv[col + 1];
                *(float2*)(g_qu + (size_t)r * D_ + col)       = make_float2(tf32rnd(q0 + u0), tf32rnd(q1 + u1));
                *(float2*)(g_qu + (size_t)(r + 8) * D_ + col) = make_float2(tf32rnd(q2 + u0), tf32rnd(q3 + u1));
                *(float2*)(g_qv + (size_t)r * D_ + col)       = make_float2(tf32rnd(q0 + v0), tf32rnd(q1 + v1));
                *(float2*)(g_qv + (size_t)(r + 8) * D_ + col) = make_float2(tf32rnd(q2 + v0), tf32rnd(q3 + v1));
            }
        }
    } else {
        float* C = (z == 1) ? g_k : (z == 2) ? g_v : (g_r + (size_t)384 * D_);
        #pragma unroll
        for (int mt = 0; mt < 2; mt++) {
            int r = m0 + wr * 32 + mt * 16 + qr;
            #pragma unroll
            for (int nt = 0; nt < 8; nt++) {
                int col = n0 + wc * 64 + nt * 8 + qc * 2;
                *(float2*)(C + (size_t)r * D_ + col) =
                    make_float2(tf32rnd(acc[mt][nt][0]), tf32rnd(acc[mt][nt][1]));
                *(float2*)(C + (size_t)(r + 8) * D_ + col) =
                    make_float2(tf32rnd(acc[mt][nt][2]), tf32rnd(acc[mt][nt][3]));
            }
        }
    }
}

// ---------------- output projection GEMM (tf32, 3-stage BK=32) ----------------
__global__ void __launch_bounds__(256) gemm_out(float* __restrict__ C)
{
    extern __shared__ float smf[];
    float* sA = smf;
    float* sB = smf + 3 * 128 * 36;
    unsigned sAa = saddr(sA), sBa = saddr(sB);

    int tid = threadIdx.x;
    int lane = tid & 31, wid = tid >> 5;
    int wr = wid >> 1, wc = wid & 1;
    int qr = lane >> 2, qc = lane & 3;
    int m0 = blockIdx.y * 128, n0 = blockIdx.x * 128;

    float acc[2][8][4];
    #pragma unroll
    for (int i = 0; i < 2; i++)
        #pragma unroll
        for (int j = 0; j < 8; j++)
            #pragma unroll
            for (int l = 0; l < 4; l++) acc[i][j][l] = 0.f;

    auto load_tiles = [&](int st, int k0) {
        unsigned da = sAa + st * (128 * 36 * 4);
        unsigned db = sBa + st * (32 * 132 * 4);
        #pragma unroll
        for (int j = 0; j < 4; j++) {
            int id = tid + j * 256;
            int ra = id >> 3, ca = (id & 7) << 2;
            cp16(da + (ra * 36 + ca) * 4, g_wv + (size_t)(m0 + ra) * D_ + k0 + ca);
            int rb = id >> 5, cb = (id & 31) << 2;
            cp16(db + (rb * 132 + cb) * 4, g_wo + (size_t)(k0 + rb) * D_ + n0 + cb);
        }
    };

    load_tiles(0, 0);  cp_commit();
    load_tiles(1, 32); cp_commit();

    for (int it = 0; it < 32; it++) {
        int st = it % 3;
        if (it < 30) cp_wait1(); else cp_wait0();
        __syncthreads();
        if (it + 2 < 32) { load_tiles((it + 2) % 3, (it + 2) << 5); cp_commit(); }

        const unsigned* cA = (const unsigned*)(sA + st * (128 * 36));
        const unsigned* cB = (const unsigned*)(sB + st * (32 * 132));
        #pragma unroll
        for (int ks = 0; ks < 4; ks++) {
            const int kk = ks * 8;
            unsigned a[2][4], bf[8][2];
            #pragma unroll
            for (int mt = 0; mt < 2; mt++) {
                int r = wr * 32 + mt * 16 + qr;
                a[mt][0] = cA[r * 36 + kk + qc];
                a[mt][1] = cA[(r + 8) * 36 + kk + qc];
                a[mt][2] = cA[r * 36 + kk + qc + 4];
                a[mt][3] = cA[(r + 8) * 36 + kk + qc + 4];
            }
            #pragma unroll
            for (int nt = 0; nt < 8; nt++) {
                int cn = wc * 64 + nt * 8 + qr;
                bf[nt][0] = cB[(kk + qc) * 132 + cn];
                bf[nt][1] = cB[(kk + qc + 4) * 132 + cn];
            }
            #pragma unroll
            for (int mt = 0; mt < 2; mt++)
                #pragma unroll
                for (int nt = 0; nt < 8; nt++)
                    mma8(acc[mt][nt], a[mt], bf[nt]);
        }
    }

    #pragma unroll
    for (int mt = 0; mt < 2; mt++) {
        int r = m0 + wr * 32 + mt * 16 + qr;
        #pragma unroll
        for (int nt = 0; nt < 8; nt++) {
            int col = n0 + wc * 64 + nt * 8 + qc * 2;
            *(float2*)(C + (size_t)r * D_ + col)       = make_float2(acc[mt][nt][0], acc[mt][nt][1]);
            *(float2*)(C + (size_t)(r + 8) * D_ + col) = make_float2(acc[mt][nt][2], acc[mt][nt][3]);
        }
    }
}

// ---------------- bd GEMM: bd[bh][i][i+d] = qv_i . R[511+d] ----------------
#define BD_SMEM ((2 * 128 * 36 * 2) * 4)
__global__ void __launch_bounds__(256) bd_mma()
{
    extern __shared__ float smf[];
    float* sA = smf;
    float* sB = smf + 2 * 128 * 36;
    unsigned sAa = saddr(sA), sBa = saddr(sB);

    int tid = threadIdx.x;
    int lane = tid & 31, wid = tid >> 5;
    int wr = wid >> 1, wc = wid & 1;
    int qr = lane >> 2, qc = lane & 3;
    int d0 = blockIdx.x * 128;
    int i0 = blockIdx.y * 128;
    int bh = blockIdx.z;
    int b = bh >> 3, h = bh & 7;

    float acc[2][8][4];
    #pragma unroll
    for (int i = 0; i < 2; i++)
        #pragma unroll
        for (int j = 0; j < 8; j++)
            #pragma unroll
            for (int l = 0; l < 4; l++) acc[i][j][l] = 0.f;

    auto load_tiles = [&](int st, int k0) {
        unsigned da = sAa + st * (128 * 36 * 4);
        unsigned db = sBa + st * (128 * 36 * 4);
        #pragma unroll
        for (int j = 0; j < 4; j++) {
            int id = tid + j * 256;
            int r = id >> 3, c = (id & 7) << 2;
            cp16(da + (r * 36 + c) * 4,
                 g_qv + (size_t)(b * L_ + i0 + r) * D_ + h * K_ + k0 + c);
            int rr = 511 + d0 + r; if (rr > W_ - 1) rr = W_ - 1;
            cp16(db + (r * 36 + c) * 4,
                 g_r + (size_t)rr * D_ + h * K_ + k0 + c);
        }
    };

    load_tiles(0, 0); cp_commit();

    for (int it = 0; it < 4; it++) {
        int st = it & 1;
        if (it + 1 < 4) { load_tiles(st ^ 1, (it + 1) << 5); cp_commit(); cp_wait1(); }
        else cp_wait0();
        __syncthreads();
        const unsigned* cA = (const unsigned*)(sA + st * (128 * 36));
        const unsigned* cB = (const unsigned*)(sB + st * (128 * 36));
        #pragma unroll
        for (int ks = 0; ks < 4; ks++) {
            const int kk = ks * 8;
            unsigned a[2][4], bf[8][2];
            #pragma unroll
            for (int mt = 0; mt < 2; mt++) {
                int r = wr * 32 + mt * 16 + qr;
                a[mt][0] = cA[r * 36 + kk + qc];
                a[mt][1] = cA[(r + 8) * 36 + kk + qc];
                a[mt][2] = cA[r * 36 + kk + qc + 4];
                a[mt][3] = cA[(r + 8) * 36 + kk + qc + 4];
            }
            #pragma unroll
            for (int nt = 0; nt < 8; nt++) {
                int cn = wc * 64 + nt * 8 + qr;
                bf[nt][0] = cB[cn * 36 + kk + qc];
                bf[nt][1] = cB[cn * 36 + kk + qc + 4];
            }
            #pragma unroll
            for (int mt = 0; mt < 2; mt++)
                #pragma unroll
                for (int nt = 0; nt < 8; nt++)
                    mma8(acc[mt][nt], a[mt], bf[nt]);
        }
        __syncthreads();
    }

    #pragma unroll
    for (int mt = 0; mt < 2; mt++) {
        int gi = i0 + wr * 32 + mt * 16 + qr;
        float* r0 = g_bd + ((size_t)(bh * L_ + gi)) * W_ + gi;
        float* r1 = g_bd + ((size_t)(bh * L_ + gi + 8)) * W_ + gi + 8;
        #pragma unroll
        for (int nt = 0; nt < 8; nt++) {
            int gd = d0 + wc * 64 + nt * 8 + qc * 2;
            if (gd <= 2048)     { r0[gd]     = acc[mt][nt][0]; r1[gd]     = acc[mt][nt][2]; }
            if (gd + 1 <= 2048) { r0[gd + 1] = acc[mt][nt][1]; r1[gd + 1] = acc[mt][nt][3]; }
        }
    }
}

// ---------------- banded flash attention: 1 block sync + 2 pair barriers / tile ----------------
// smem word layout:
//  Qs(u32)  [64*132]            @0      .. 8448
//  Kf(f32) 2x[64*132] = 16896   @8448   .. 25344
//  Vf(f32) 2x[64*136] = 17408   @25344  .. 42752
//  Bd(f32) 2x[64*68]  = 8704    @42752  .. 51456
//  Ssm(f32) [64*68]   = 4352    @51456  .. 55808
//  mrow/lrow/arow 3*64 = 192    @55808  .. 56000
#define ATT_SMEM (56000 * 4)
__global__ void __launch_bounds__(256) attn_mma(
    const float* __restrict__ cacheK, const float* __restrict__ cacheV,
    const int* __restrict__ posp)
{
    extern __shared__ unsigned smu[];
    unsigned* Qs = smu;
    float* Kf  = (float*)(smu + 8448);
    float* Vf  = (float*)(smu + 25344);
    float* Bd  = (float*)(smu + 42752);
    float* Ssm = (float*)(smu + 51456);
    float* mrow = (float*)(smu + 55808);
    float* lrow = mrow + 64;
    float* arow = lrow + 64;
    unsigned Ka = saddr(Kf), Va = saddr(Vf), Ba = saddr(Bd);

    int tid = threadIdx.x;
    int lane = tid & 31, wid = tid >> 5;
    int wr = wid >> 1, wc = wid & 1;
    int qr = lane >> 2, qc = lane & 3;
    int bh = blockIdx.y;
    int b = bh >> 3, h = bh & 7;
    int i0 = blockIdx.x * 64;
    int inval = M_ - posp[0]; if (inval < 0) inval = 0;
    const int barid = 1 + wr;      // named barrier per warp-pair

    auto load_kv = [&](int kt, int st) {
        int j0 = i0 + kt * 64;
        unsigned kd = Ka + st * (64 * 132 * 4);
        unsigned vd = Va + st * (64 * 136 * 4);
        #pragma unroll
        for (int j = 0; j < 8; j++) {
            int id = tid + j * 256;
            int r = id >> 5, c = (id & 31) << 2;
            int jj = j0 + r;
            const float *kp, *vp;
            if (jj < M_) {
                size_t off = ((size_t)bh * M_ + jj) * K_ + c;
                kp = cacheK + off; vp = cacheV + off;
            } else {
                size_t off = ((size_t)(b * L_ + (jj - M_))) * D_ + h * K_ + c;
                kp = g_k + off; vp = g_v + off;
            }
            cp16(kd + (r * 132 + c) * 4, kp);
            cp16(vd + (r * 136 + c) * 4, vp);
        }
        unsigned bd = Ba + st * (64 * 68 * 4);
        const float* bdb = g_bd + ((size_t)(bh * L_ + i0)) * W_ + j0;
        #pragma unroll
        for (int j = 0; j < 4; j++) {
            int id = tid + j * 256;
            int r = id >> 4, c = (id & 15) << 2;
            cp16(bd + (r * 68 + c) * 4, bdb + (size_t)r * W_ + c);
        }
    };

    load_kv(0, 0); cp_commit();

    // Q tile (pre-rounded qu) -> smem, plain copy
    const float* qbase = g_qu + ((size_t)(b * L_ + i0)) * D_ + h * K_;
    #pragma unroll
    for (int l = 0; l < 8; l++) {
        int idx = tid + l * 256;
        int r = idx >> 5, c = (idx & 31) << 2;
        *(uint4*)&Qs[r * 132 + c] = *(const uint4*)(qbase + (size_t)r * D_ + c);
    }
    if (tid < 64) { mrow[tid] = -1e30f; lrow[tid] = 0.f; }

    float oacc[8][4];
    #pragma unroll
    for (int i = 0; i < 8; i++)
        #pragma unroll
        for (int j = 0; j < 4; j++) oacc[i][j] = 0.f;

    // pair-local softmax mapping: pair wr owns rows 16wr..16wr+15
    int ptid = tid & 63;
    int srow = wr * 16 + (ptid >> 2);
    int sg = ptid & 3;
    int r = wr * 16 + qr;

    for (int kt = 0; kt < 33; kt++) {
        int st = kt & 1;
        int j0 = i0 + kt * 64;

        cp_wait0();
        __syncthreads();                       // loads visible + buffers free
        if (kt + 1 < 33) { load_kv(kt + 1, st ^ 1); cp_commit(); }

        const float* cKf = Kf + st * (64 * 132);
        const float* cVf = Vf + st * (64 * 136);
        const float* cB = Bd + st * (64 * 68);

        // phase A: S = (Q+u) K^T   (K converted at fragment load)
        float s[4][4];
        #pragma unroll
        for (int i = 0; i < 4; i++)
            #pragma unroll
            for (int j = 0; j < 4; j++) s[i][j] = 0.f;
        #pragma unroll
        for (int ks = 0; ks < 16; ks++) {
            const int kk = ks * 8;
            unsigned a[4], bf[4][2];
            a[0] = Qs[r * 132 + kk + qc];
            a[1] = Qs[(r + 8) * 132 + kk + qc];
            a[2] = Qs[r * 132 + kk + qc + 4];
            a[3] = Qs[(r + 8) * 132 + kk + qc + 4];
            #pragma unroll
            for (int nt = 0; nt < 4; nt++) {
                int n = wc * 32 + nt * 8 + qr;
                bf[nt][0] = tf32cvt(cKf[n * 132 + kk + qc]);
                bf[nt][1] = tf32cvt(cKf[n * 132 + kk + qc + 4]);
            }
            #pragma unroll
            for (int nt = 0; nt < 4; nt++) mma8(s[nt], a, bf[nt]);
        }
        // add bd + mask, write S to smem (own pair rows only)
        {
            int gi0 = i0 + r, gi1 = gi0 + 8;
            #pragma unroll
            for (int nt = 0; nt < 4; nt++) {
                int cbase = wc * 32 + nt * 8 + qc * 2;
                #pragma unroll
                for (int e = 0; e < 2; e++) {
                    int cc = cbase + e;
                    int gj = j0 + cc;
                    int dd0 = gj - gi0, dd1 = gj - gi1;
                    float b0 = cB[r * 68 + cc];
                    float b1 = cB[(r + 8) * 68 + cc];
                    float v0 = (dd0 >= 0 && dd0 <= 2048 && gj >= inval) ? (s[nt][e] + b0) : -1e30f;
                    float v1 = (dd1 >= 0 && dd1 <= 2048 && gj >= inval) ? (s[nt][2 + e] + b1) : -1e30f;
                    Ssm[r * 68 + cc] = v0;
                    Ssm[(r + 8) * 68 + cc] = v1;
                }
            }
        }
        asm volatile("bar.sync %0, 64;" :: "r"(barid) : "memory");

        // pair-local online softmax (4 lanes / row); P stored as tf32 bits
        {
            float* Sr = Ssm + srow * 68 + sg * 16;
            float mx = -1e30f;
            #pragma unroll
            for (int c2 = 0; c2 < 16; c2++) mx = fmaxf(mx, Sr[c2]);
            mx = fmaxf(mx, __shfl_xor_sync(0xffffffffu, mx, 1));
            mx = fmaxf(mx, __shfl_xor_sync(0xffffffffu, mx, 2));
            float mold = mrow[srow];
            float mnew = fmaxf(mold, mx);
            float sum = 0.f;
            #pragma unroll
            for (int c2 = 0; c2 < 16; c2++) {
                float p = __expf(Sr[c2] - mnew);
                ((unsigned*)Sr)[c2] = tf32cvt(p);
                sum += p;
            }
            sum += __shfl_xor_sync(0xffffffffu, sum, 1);
            sum += __shfl_xor_sync(0xffffffffu, sum, 2);
            if (sg == 0) {
                float alpha = __expf(mold - mnew);
                arow[srow] = alpha;
                lrow[srow] = lrow[srow] * alpha + sum;
                mrow[srow] = mnew;
            }
        }
        asm volatile("bar.sync %0, 64;" :: "r"(barid) : "memory");

        // phase C: rescale + O += P @ V   (V converted at fragment load)
        {
            float al0 = arow[r], al1 = arow[r + 8];
            #pragma unroll
            for (int nt = 0; nt < 8; nt++) {
                oacc[nt][0] *= al0; oacc[nt][1] *= al0;
                oacc[nt][2] *= al1; oacc[nt][3] *= al1;
            }
            const unsigned* Pu = (const unsigned*)Ssm;
            #pragma unroll
            for (int ks = 0; ks < 8; ks++) {
                const int kk = ks * 8;
                unsigned a[4], bf[8][2];
                a[0] = Pu[r * 68 + kk + qc];
                a[1] = Pu[(r + 8) * 68 + kk + qc];
                a[2] = Pu[r * 68 + kk + qc + 4];
                a[3] = Pu[(r + 8) * 68 + kk + qc + 4];
                #pragma unroll
                for (int nt = 0; nt < 8; nt++) {
                    int n = wc * 64 + nt * 8 + qr;
                    bf[nt][0] = tf32cvt(cVf[(kk + qc) * 136 + n]);
                    bf[nt][1] = tf32cvt(cVf[(kk + qc + 4) * 136 + n]);
                }
                #pragma unroll
                for (int nt = 0; nt < 8; nt++) mma8(oacc[nt], a, bf[nt]);
            }
        }
        // no end-of-tile block sync: top-of-next-tile __syncthreads covers reuse
    }

    // epilogue: normalize, round to tf32, write wv
    {
        float inv0 = 1.0f / lrow[r];
        float inv1 = 1.0f / lrow[r + 8];
        float* o0 = g_wv + ((size_t)(b * L_ + i0 + r)) * D_ + h * K_;
        float* o1 = g_wv + ((size_t)(b * L_ + i0 + r + 8)) * D_ + h * K_;
        #pragma unroll
        for (int nt = 0; nt < 8; nt++) {
            int col = wc * 64 + nt * 8 + qc * 2;
            *(float2*)(o0 + col) = make_float2(tf32rnd(oacc[nt][0] * inv0), tf32rnd(oacc[nt][1] * inv0));
            *(float2*)(o1 + col) = make_float2(tf32rnd(oacc[nt][2] * inv1), tf32rnd(oacc[nt][3] * inv1));
        }
    }
}

// ---------------- launch ----------------
extern "C" void kernel_launch(void* const* d_in, const int* in_sizes, int n_in,
                              void* d_out, int out_size)
{
    const float* x      = (const float*)d_in[0];
    const int*   pos    = (const int*)  d_in[1];
    const float* cacheK = (const float*)d_in[2];
    const float* cacheV = (const float*)d_in[3];
    const float* g_rms  = (const float*)d_in[4];
    const float* Wq     = (const float*)d_in[5];
    const float* Wk     = (const float*)d_in[6];
    const float* Wv     = (const float*)d_in[7];
    const float* Wr     = (const float*)d_in[8];
    const float* xlu    = (const float*)d_in[9];
    const float* xlv    = (const float*)d_in[10];
    const float* Wo     = (const float*)d_in[11];
    float* out          = (float*)d_out;

    float* p_xt;
    cudaGetSymbolAddress((void**)&p_xt, g_xt);

    cudaFuncSetAttribute(gemm_qkvr, cudaFuncAttributeMaxDynamicSharedMemorySize, GEMM_SMEM);
    cudaFuncSetAttribute(gemm_out,  cudaFuncAttributeMaxDynamicSharedMemorySize, GEMM_SMEM);
    cudaFuncSetAttribute(bd_mma,    cudaFuncAttributeMaxDynamicSharedMemorySize, BD_SMEM);
    cudaFuncSetAttribute(attn_mma,  cudaFuncAttributeMaxDynamicSharedMemorySize, ATT_SMEM);

    const int NW4 = (D_ * D_) / 4;

    // 0) pre-round all 5 weights in one launch
    cvt5<<<dim3(NW4 / 256, 5), 256>>>(Wq, Wk, Wv, Wr, Wo);

    // 1) RMSNorm (tf32 out) + sinusoid rows >= 384
    rmsnorm_kernel<<<B_ * L_, 256>>>(x, g_rms, p_xt);
    sinusoid_kernel<<<(W_ - 384) / 64, 256>>>();

    // 2) fused Q/K/V + R projections (Q emits qu/qv directly)
    gemm_qkvr<<<dim3(D_ / 128, 17, 4), 256, GEMM_SMEM>>>(xlu, xlv);

    // 3) bd scores
    bd_mma<<<dim3(17, 4, 32), 256, BD_SMEM>>>();

    // 4) banded flash attention
    attn_mma<<<dim3(L_ / 64, B_ * H_), 256, ATT_SMEM>>>(cacheK, cacheV, pos);

    // 5) output projection
    gemm_out<<<dim3(D_ / 128, (B_ * L_) / 128), 256, GEMM_SMEM>>>(out);
}

// round 11
// speedup vs baseline: 1.2862x; 1.0144x over previous
#include <cuda_runtime.h>
#include <math.h>

// Problem constants
#define B_ 4
#define L_ 512
#define M_ 2048
#define D_ 1024
#define H_ 8
#define K_ 128
#define W_ 2560
#define INV_TAU 0.08838834764831845f

// -------- scratch (device globals; no allocation allowed) --------
__device__ float g_xt[(size_t)B_ * L_ * D_];        // rmsnormed x (tf32-rounded)
__device__ float g_k [(size_t)B_ * L_ * D_];        // (tf32)
__device__ float g_v [(size_t)B_ * L_ * D_];        // (tf32)
__device__ float g_qu[(size_t)B_ * L_ * D_];        // rnd(q/tau + xl_u)
__device__ float g_qv[(size_t)B_ * L_ * D_];        // rnd(q/tau + xl_v)
__device__ float g_sin[(size_t)W_ * D_];            // (tf32; rows >=384 only)
__device__ float g_r [(size_t)W_ * D_];             // (tf32; rows >=384 only)
__device__ float g_bd[(size_t)B_ * H_ * L_ * W_];   // bd[b,h,i,j] absolute-key, fp32
__device__ float g_wv[(size_t)B_ * L_ * D_];        // attn out (tf32)
__device__ float g_wq[(size_t)D_ * D_];             // rounded weights
__device__ float g_wk[(size_t)D_ * D_];
__device__ float g_wvw[(size_t)D_ * D_];
__device__ float g_wr[(size_t)D_ * D_];
__device__ float g_wo[(size_t)D_ * D_];

// ---------------- helpers ----------------
__device__ __forceinline__ unsigned tf32cvt(float f) {
    unsigned r;
    asm("cvt.rna.tf32.f32 %0, %1;" : "=r"(r) : "f"(f));
    return r;
}
__device__ __forceinline__ float tf32rnd(float f) { return __uint_as_float(tf32cvt(f)); }
__device__ __forceinline__ void mma8(float* c, const unsigned* a, const unsigned* b) {
    asm("mma.sync.aligned.m16n8k8.row.col.f32.tf32.tf32.f32 "
        "{%0,%1,%2,%3},{%4,%5,%6,%7},{%8,%9},{%0,%1,%2,%3};"
        : "+f"(c[0]), "+f"(c[1]), "+f"(c[2]), "+f"(c[3])
        : "r"(a[0]), "r"(a[1]), "r"(a[2]), "r"(a[3]), "r"(b[0]), "r"(b[1]));
}
__device__ __forceinline__ void cp16(unsigned dst, const void* src) {
    asm volatile("cp.async.cg.shared.global [%0], [%1], 16;" :: "r"(dst), "l"(src));
}
__device__ __forceinline__ void cp_commit() { asm volatile("cp.async.commit_group;"); }
__device__ __forceinline__ void cp_wait1()  { asm volatile("cp.async.wait_group 1;"); }
__device__ __forceinline__ void cp_wait0()  { asm volatile("cp.async.wait_group 0;"); }
__device__ __forceinline__ unsigned saddr(const void* p) {
    return (unsigned)__cvta_generic_to_shared(p);
}

// ---------------- fused prep: weight rounding + RMSNorm + sinusoid ----------------
// blocks [0, 5120): weight cvt (5 x 1024 blocks)
// blocks [5120, 7168): rmsnorm rows
// blocks [7168, 7202): sinusoid rows 384.. (34 blocks x 64 rows)
__global__ void prep_kernel(const float* __restrict__ x, const float* __restrict__ grms,
                            const float* __restrict__ wq, const float* __restrict__ wk,
                            const float* __restrict__ wv, const float* __restrict__ wr,
                            const float* __restrict__ wo)
{
    __shared__ double shd[512];
    int bx = blockIdx.x;
    int tid = threadIdx.x;

    if (bx < 5120) {
        int wsel = bx >> 10;
        const float* src; float* dst;
        switch (wsel) {
            case 0: src = wq; dst = g_wq;  break;
            case 1: src = wk; dst = g_wk;  break;
            case 2: src = wv; dst = g_wvw; break;
            case 3: src = wr; dst = g_wr;  break;
            default: src = wo; dst = g_wo; break;
        }
        int i = (bx & 1023) * 256 + tid;
        float4 v = ((const float4*)src)[i];
        ((uint4*)dst)[i] = make_uint4(tf32cvt(v.x), tf32cvt(v.y), tf32cvt(v.z), tf32cvt(v.w));
    } else if (bx < 7168) {
        // RMSNorm row
        int row = bx - 5120;
        float* ws = (float*)shd;
        const float4* xr = (const float4*)(x + (size_t)row * D_);
        float4 v = xr[tid];
        float ss = v.x * v.x + v.y * v.y + v.z * v.z + v.w * v.w;
        #pragma unroll
        for (int o = 16; o > 0; o >>= 1) ss += __shfl_xor_sync(0xffffffffu, ss, o);
        if ((tid & 31) == 0) ws[tid >> 5] = ss;
        __syncthreads();
        if (tid < 8) {
            float t = ws[tid];
            #pragma unroll
            for (int o = 4; o > 0; o >>= 1) t += __shfl_xor_sync(0xffu, t, o);
            if (tid == 0) ws[0] = t;
        }
        __syncthreads();
        float scale = rsqrtf(ws[0] * (1.0f / (float)D_) + 1e-6f);
        float4 gv = ((const float4*)grms)[tid];
        *(uint4*)(g_xt + (size_t)row * D_ + tid * 4) = make_uint4(
            tf32cvt(v.x * scale * gv.x), tf32cvt(v.y * scale * gv.y),
            tf32cvt(v.z * scale * gv.z), tf32cvt(v.w * scale * gv.w));
    } else {
        // sinusoid, 64 rows per block starting at 384
        int w0 = 384 + (bx - 7168) * 64;
        for (int i = tid; i < 512; i += 256)
            shd[i] = exp(-(double)i * (9.210340371976184 / 512.0));
        __syncthreads();
        for (int e = tid; e < 64 * 512; e += 256) {
            int w = w0 + (e >> 9);
            int i = e & 511;
            int p = (W_ - 1) - w;
            double ang = (double)p * shd[i];
            double t = ang * 0.15915494309189535;
            t -= floor(t);
            float th = (float)(t * 6.283185307179586);
            float s, c;
            sincosf(th, &s, &c);
            g_sin[(size_t)w * D_ + i]       = tf32rnd(s);
            g_sin[(size_t)w * D_ + 512 + i] = tf32rnd(c);
        }
    }
}

// ---------------- fused QKV + R projection GEMM (tf32, 3-stage BK=32) ----------------
// grid (8, 17, 4): z=0 -> Q (emits qu/qv), z=1 K, z=2 V (y<16), z=3 R rows 384..2559
#define GEMM_SMEM (3 * (128 * 36 + 32 * 132) * 4)
__global__ void __launch_bounds__(256) gemm_qkvr(const float* __restrict__ xlu,
                                                 const float* __restrict__ xlv)
{
    const float* A; const float* Bm;
    int z = blockIdx.z;
    if (z == 0)      { A = g_xt; Bm = g_wq;  }
    else if (z == 1) { A = g_xt; Bm = g_wk;  }
    else if (z == 2) { A = g_xt; Bm = g_wvw; }
    else             { A = g_sin + (size_t)384 * D_; Bm = g_wr; }
    if (z < 3 && blockIdx.y == 16) return;

    extern __shared__ float smf[];
    float* sA = smf;                        // 3 x [128][36]
    float* sB = smf + 3 * 128 * 36;         // 3 x [32][132]
    unsigned sAa = saddr(sA), sBa = saddr(sB);

    int tid = threadIdx.x;
    int lane = tid & 31, wid = tid >> 5;
    int wr = wid >> 1, wc = wid & 1;
    int qr = lane >> 2, qc = lane & 3;
    int m0 = blockIdx.y * 128, n0 = blockIdx.x * 128;

    float acc[2][8][4];
    #pragma unroll
    for (int i = 0; i < 2; i++)
        #pragma unroll
        for (int j = 0; j < 8; j++)
            #pragma unroll
            for (int l = 0; l < 4; l++) acc[i][j][l] = 0.f;

    auto load_tiles = [&](int st, int k0) {
        unsigned da = sAa + st * (128 * 36 * 4);
        unsigned db = sBa + st * (32 * 132 * 4);
        #pragma unroll
        for (int j = 0; j < 4; j++) {
            int id = tid + j * 256;
            int ra = id >> 3, ca = (id & 7) << 2;
            cp16(da + (ra * 36 + ca) * 4, A + (size_t)(m0 + ra) * D_ + k0 + ca);
            int rb = id >> 5, cb = (id & 31) << 2;
            cp16(db + (rb * 132 + cb) * 4, Bm + (size_t)(k0 + rb) * D_ + n0 + cb);
        }
    };

    load_tiles(0, 0);  cp_commit();
    load_tiles(1, 32); cp_commit();

    for (int it = 0; it < 32; it++) {
        int st = it % 3;
        if (it < 30) cp_wait1(); else cp_wait0();
        __syncthreads();
        if (it + 2 < 32) { load_tiles((it + 2) % 3, (it + 2) << 5); cp_commit(); }

        const unsigned* cA = (const unsigned*)(sA + st * (128 * 36));
        const unsigned* cB = (const unsigned*)(sB + st * (32 * 132));
        #pragma unroll
        for (int ks = 0; ks < 4; ks++) {
            const int kk = ks * 8;
            unsigned a[2][4], bf[8][2];
            #pragma unroll
            for (int mt = 0; mt < 2; mt++) {
                int r = wr * 32 + mt * 16 + qr;
                a[mt][0] = cA[r * 36 + kk + qc];
                a[mt][1] = cA[(r + 8) * 36 + kk + qc];
                a[mt][2] = cA[r * 36 + kk + qc + 4];
                a[mt][3] = cA[(r + 8) * 36 + kk + qc + 4];
            }
            #pragma unroll
            for (int nt = 0; nt < 8; nt++) {
                int cn = wc * 64 + nt * 8 + qr;
                bf[nt][0] = cB[(kk + qc) * 132 + cn];
                bf[nt][1] = cB[(kk + qc + 4) * 132 + cn];
            }
            #pragma unroll
            for (int mt = 0; mt < 2; mt++)
                #pragma unroll
                for (int nt = 0; nt < 8; nt++)
                    mma8(acc[mt][nt], a[mt], bf[nt]);
        }
    }

    // epilogue
    if (z == 0) {
        #pragma unroll
        for (int mt = 0; mt < 2; mt++) {
            int r = m0 + wr * 32 + mt * 16 + qr;
            #pragma unroll
            for (int nt = 0; nt < 8; nt++) {
                int col = n0 + wc * 64 + nt * 8 + qc * 2;
                float q0 = acc[mt][nt][0] * INV_TAU, q1 = acc[mt][nt][1] * INV_TAU;
                float q2 = acc[mt][nt][2] * INV_TAU, q3 = acc[mt][nt][3] * INV_TAU;
                float u0 = xlu[col], u1 = xlu[col + 1];
                float v0 = xlv[col], v1 = xlv[col + 1];
                *(float2*)(g_qu + (size_t)r * D_ + col)       = make_float2(tf32rnd(q0 + u0), tf32rnd(q1 + u1));
                *(float2*)(g_qu + (size_t)(r + 8) * D_ + col) = make_float2(tf32rnd(q2 + u0), tf32rnd(q3 + u1));
                *(float2*)(g_qv + (size_t)r * D_ + col)       = make_float2(tf32rnd(q0 + v0), tf32rnd(q1 + v1));
                *(float2*)(g_qv + (size_t)(r + 8) * D_ + col) = make_float2(tf32rnd(q2 + v0), tf32rnd(q3 + v1));
            }
        }
    } else {
        float* C = (z == 1) ? g_k : (z == 2) ? g_v : (g_r + (size_t)384 * D_);
        #pragma unroll
        for (int mt = 0; mt < 2; mt++) {
            int r = m0 + wr * 32 + mt * 16 + qr;
            #pragma unroll
            for (int nt = 0; nt < 8; nt++) {
                int col = n0 + wc * 64 + nt * 8 + qc * 2;
                *(float2*)(C + (size_t)r * D_ + col) =
                    make_float2(tf32rnd(acc[mt][nt][0]), tf32rnd(acc[mt][nt][1]));
                *(float2*)(C + (size_t)(r + 8) * D_ + col) =
                    make_float2(tf32rnd(acc[mt][nt][2]), tf32rnd(acc[mt][nt][3]));
            }
        }
    }
}

// ---------------- output projection GEMM (tf32, 3-stage BK=32) ----------------
__global__ void __launch_bounds__(256) gemm_out(float* __restrict__ C)
{
    extern __shared__ float smf[];
    float* sA = smf;
    float* sB = smf + 3 * 128 * 36;
    unsigned sAa = saddr(sA), sBa = saddr(sB);

    int tid = threadIdx.x;
    int lane = tid & 31, wid = tid >> 5;
    int wr = wid >> 1, wc = wid & 1;
    int qr = lane >> 2, qc = lane & 3;
    int m0 = blockIdx.y * 128, n0 = blockIdx.x * 128;

    float acc[2][8][4];
    #pragma unroll
    for (int i = 0; i < 2; i++)
        #pragma unroll
        for (int j = 0; j < 8; j++)
            #pragma unroll
            for (int l = 0; l < 4; l++) acc[i][j][l] = 0.f;

    auto load_tiles = [&](int st, int k0) {
        unsigned da = sAa + st * (128 * 36 * 4);
        unsigned db = sBa + st * (32 * 132 * 4);
        #pragma unroll
        for (int j = 0; j < 4; j++) {
            int id = tid + j * 256;
            int ra = id >> 3, ca = (id & 7) << 2;
            cp16(da + (ra * 36 + ca) * 4, g_wv + (size_t)(m0 + ra) * D_ + k0 + ca);
            int rb = id >> 5, cb = (id & 31) << 2;
            cp16(db + (rb * 132 + cb) * 4, g_wo + (size_t)(k0 + rb) * D_ + n0 + cb);
        }
    };

    load_tiles(0, 0);  cp_commit();
    load_tiles(1, 32); cp_commit();

    for (int it = 0; it < 32; it++) {
        int st = it % 3;
        if (it < 30) cp_wait1(); else cp_wait0();
        __syncthreads();
        if (it + 2 < 32) { load_tiles((it + 2) % 3, (it + 2) << 5); cp_commit(); }

        const unsigned* cA = (const unsigned*)(sA + st * (128 * 36));
        const unsigned* cB = (const unsigned*)(sB + st * (32 * 132));
        #pragma unroll
        for (int ks = 0; ks < 4; ks++) {
            const int kk = ks * 8;
            unsigned a[2][4], bf[8][2];
            #pragma unroll
            for (int mt = 0; mt < 2; mt++) {
                int r = wr * 32 + mt * 16 + qr;
                a[mt][0] = cA[r * 36 + kk + qc];
                a[mt][1] = cA[(r + 8) * 36 + kk + qc];
                a[mt][2] = cA[r * 36 + kk + qc + 4];
                a[mt][3] = cA[(r + 8) * 36 + kk + qc + 4];
            }
            #pragma unroll
            for (int nt = 0; nt < 8; nt++) {
                int cn = wc * 64 + nt * 8 + qr;
                bf[nt][0] = cB[(kk + qc) * 132 + cn];
                bf[nt][1] = cB[(kk + qc + 4) * 132 + cn];
            }
            #pragma unroll
            for (int mt = 0; mt < 2; mt++)
                #pragma unroll
                for (int nt = 0; nt < 8; nt++)
                    mma8(acc[mt][nt], a[mt], bf[nt]);
        }
    }

    #pragma unroll
    for (int mt = 0; mt < 2; mt++) {
        int r = m0 + wr * 32 + mt * 16 + qr;
        #pragma unroll
        for (int nt = 0; nt < 8; nt++) {
            int col = n0 + wc * 64 + nt * 8 + qc * 2;
            *(float2*)(C + (size_t)r * D_ + col)       = make_float2(acc[mt][nt][0], acc[mt][nt][1]);
            *(float2*)(C + (size_t)(r + 8) * D_ + col) = make_float2(acc[mt][nt][2], acc[mt][nt][3]);
        }
    }
}

// ---------------- bd GEMM: bd[bh][i][i+d] = qv_i . R[511+d] ----------------
#define BD_SMEM ((2 * 128 * 36 * 2) * 4)
__global__ void __launch_bounds__(256) bd_mma()
{
    extern __shared__ float smf[];
    float* sA = smf;
    float* sB = smf + 2 * 128 * 36;
    unsigned sAa = saddr(sA), sBa = saddr(sB);

    int tid = threadIdx.x;
    int lane = tid & 31, wid = tid >> 5;
    int wr = wid >> 1, wc = wid & 1;
    int qr = lane >> 2, qc = lane & 3;
    int d0 = blockIdx.x * 128;
    int i0 = blockIdx.y * 128;
    int bh = blockIdx.z;
    int b = bh >> 3, h = bh & 7;

    float acc[2][8][4];
    #pragma unroll
    for (int i = 0; i < 2; i++)
        #pragma unroll
        for (int j = 0; j < 8; j++)
            #pragma unroll
            for (int l = 0; l < 4; l++) acc[i][j][l] = 0.f;

    auto load_tiles = [&](int st, int k0) {
        unsigned da = sAa + st * (128 * 36 * 4);
        unsigned db = sBa + st * (128 * 36 * 4);
        #pragma unroll
        for (int j = 0; j < 4; j++) {
            int id = tid + j * 256;
            int r = id >> 3, c = (id & 7) << 2;
            cp16(da + (r * 36 + c) * 4,
                 g_qv + (size_t)(b * L_ + i0 + r) * D_ + h * K_ + k0 + c);
            int rr = 511 + d0 + r; if (rr > W_ - 1) rr = W_ - 1;
            cp16(db + (r * 36 + c) * 4,
                 g_r + (size_t)rr * D_ + h * K_ + k0 + c);
        }
    };

    load_tiles(0, 0); cp_commit();

    for (int it = 0; it < 4; it++) {
        int st = it & 1;
        if (it + 1 < 4) { load_tiles(st ^ 1, (it + 1) << 5); cp_commit(); cp_wait1(); }
        else cp_wait0();
        __syncthreads();
        const unsigned* cA = (const unsigned*)(sA + st * (128 * 36));
        const unsigned* cB = (const unsigned*)(sB + st * (128 * 36));
        #pragma unroll
        for (int ks = 0; ks < 4; ks++) {
            const int kk = ks * 8;
            unsigned a[2][4], bf[8][2];
            #pragma unroll
            for (int mt = 0; mt < 2; mt++) {
                int r = wr * 32 + mt * 16 + qr;
                a[mt][0] = cA[r * 36 + kk + qc];
                a[mt][1] = cA[(r + 8) * 36 + kk + qc];
                a[mt][2] = cA[r * 36 + kk + qc + 4];
                a[mt][3] = cA[(r + 8) * 36 + kk + qc + 4];
            }
            #pragma unroll
            for (int nt = 0; nt < 8; nt++) {
                int cn = wc * 64 + nt * 8 + qr;
                bf[nt][0] = cB[cn * 36 + kk + qc];
                bf[nt][1] = cB[cn * 36 + kk + qc + 4];
            }
            #pragma unroll
            for (int mt = 0; mt < 2; mt++)
                #pragma unroll
                for (int nt = 0; nt < 8; nt++)
                    mma8(acc[mt][nt], a[mt], bf[nt]);
        }
        __syncthreads();
    }

    #pragma unroll
    for (int mt = 0; mt < 2; mt++) {
        int gi = i0 + wr * 32 + mt * 16 + qr;
        float* r0 = g_bd + ((size_t)(bh * L_ + gi)) * W_ + gi;
        float* r1 = g_bd + ((size_t)(bh * L_ + gi + 8)) * W_ + gi + 8;
        #pragma unroll
        for (int nt = 0; nt < 8; nt++) {
            int gd = d0 + wc * 64 + nt * 8 + qc * 2;
            if (gd <= 2048)     { r0[gd]     = acc[mt][nt][0]; r1[gd]     = acc[mt][nt][2]; }
            if (gd + 1 <= 2048) { r0[gd + 1] = acc[mt][nt][1]; r1[gd + 1] = acc[mt][nt][3]; }
        }
    }
}

// ---------------- banded flash attention: Q fragments hoisted to registers ----------------
// smem word layout:
//  Qs(u32)  [64*132]            @0      .. 8448   (staging only)
//  Kf(f32) 2x[64*132] = 16896   @8448   .. 25344
//  Vf(f32) 2x[64*136] = 17408   @25344  .. 42752
//  Bd(f32) 2x[64*68]  = 8704    @42752  .. 51456
//  Ssm(f32) [64*68]   = 4352    @51456  .. 55808
//  mrow/lrow/arow 3*64 = 192    @55808  .. 56000
#define ATT_SMEM (56000 * 4)
__global__ void __launch_bounds__(256, 1) attn_mma(
    const float* __restrict__ cacheK, const float* __restrict__ cacheV,
    const int* __restrict__ posp)
{
    extern __shared__ unsigned smu[];
    unsigned* Qs = smu;
    float* Kf  = (float*)(smu + 8448);
    float* Vf  = (float*)(smu + 25344);
    float* Bd  = (float*)(smu + 42752);
    float* Ssm = (float*)(smu + 51456);
    float* mrow = (float*)(smu + 55808);
    float* lrow = mrow + 64;
    float* arow = lrow + 64;
    unsigned Ka = saddr(Kf), Va = saddr(Vf), Ba = saddr(Bd);

    int tid = threadIdx.x;
    int lane = tid & 31, wid = tid >> 5;
    int wr = wid >> 1, wc = wid & 1;
    int qr = lane >> 2, qc = lane & 3;
    int bh = blockIdx.y;
    int b = bh >> 3, h = bh & 7;
    int i0 = blockIdx.x * 64;
    int inval = M_ - posp[0]; if (inval < 0) inval = 0;
    const int barid = 1 + wr;      // named barrier per warp-pair

    auto load_kv = [&](int kt, int st) {
        int j0 = i0 + kt * 64;
        unsigned kd = Ka + st * (64 * 132 * 4);
        unsigned vd = Va + st * (64 * 136 * 4);
        #pragma unroll
        for (int j = 0; j < 8; j++) {
            int id = tid + j * 256;
            int r = id >> 5, c = (id & 31) << 2;
            int jj = j0 + r;
            const float *kp, *vp;
            if (jj < M_) {
                size_t off = ((size_t)bh * M_ + jj) * K_ + c;
                kp = cacheK + off; vp = cacheV + off;
            } else {
                size_t off = ((size_t)(b * L_ + (jj - M_))) * D_ + h * K_ + c;
                kp = g_k + off; vp = g_v + off;
            }
            cp16(kd + (r * 132 + c) * 4, kp);
            cp16(vd + (r * 136 + c) * 4, vp);
        }
        unsigned bd = Ba + st * (64 * 68 * 4);
        const float* bdb = g_bd + ((size_t)(bh * L_ + i0)) * W_ + j0;
        #pragma unroll
        for (int j = 0; j < 4; j++) {
            int id = tid + j * 256;
            int r = id >> 4, c = (id & 15) << 2;
            cp16(bd + (r * 68 + c) * 4, bdb + (size_t)r * W_ + c);
        }
    };

    load_kv(0, 0); cp_commit();

    // Q tile (pre-rounded qu) -> smem staging, then into registers
    const float* qbase = g_qu + ((size_t)(b * L_ + i0)) * D_ + h * K_;
    #pragma unroll
    for (int l = 0; l < 8; l++) {
        int idx = tid + l * 256;
        int r = idx >> 5, c = (idx & 31) << 2;
        *(uint4*)&Qs[r * 132 + c] = *(const uint4*)(qbase + (size_t)r * D_ + c);
    }
    if (tid < 64) { mrow[tid] = -1e30f; lrow[tid] = 0.f; }
    __syncthreads();

    int r = wr * 16 + qr;
    unsigned qa[16][4];                       // Q fragments, invariant across tiles
    #pragma unroll
    for (int ks = 0; ks < 16; ks++) {
        const int kk = ks * 8;
        qa[ks][0] = Qs[r * 132 + kk + qc];
        qa[ks][1] = Qs[(r + 8) * 132 + kk + qc];
        qa[ks][2] = Qs[r * 132 + kk + qc + 4];
        qa[ks][3] = Qs[(r + 8) * 132 + kk + qc + 4];
    }

    float oacc[8][4];
    #pragma unroll
    for (int i = 0; i < 8; i++)
        #pragma unroll
        for (int j = 0; j < 4; j++) oacc[i][j] = 0.f;

    // pair-local softmax mapping: pair wr owns rows 16wr..16wr+15
    int ptid = tid & 63;
    int srow = wr * 16 + (ptid >> 2);
    int sg = ptid & 3;

    for (int kt = 0; kt < 33; kt++) {
        int st = kt & 1;
        int j0 = i0 + kt * 64;

        cp_wait0();
        __syncthreads();                       // loads visible + buffers free
        if (kt + 1 < 33) { load_kv(kt + 1, st ^ 1); cp_commit(); }

        const float* cKf = Kf + st * (64 * 132);
        const float* cVf = Vf + st * (64 * 136);
        const float* cB = Bd + st * (64 * 68);

        // phase A: S = (Q+u) K^T   (Q from registers; K converted at fragment load)
        float s[4][4];
        #pragma unroll
        for (int i = 0; i < 4; i++)
            #pragma unroll
            for (int j = 0; j < 4; j++) s[i][j] = 0.f;
        #pragma unroll
        for (int ks = 0; ks < 16; ks++) {
            const int kk = ks * 8;
            unsigned bf[4][2];
            #pragma unroll
            for (int nt = 0; nt < 4; nt++) {
                int n = wc * 32 + nt * 8 + qr;
                bf[nt][0] = tf32cvt(cKf[n * 132 + kk + qc]);
                bf[nt][1] = tf32cvt(cKf[n * 132 + kk + qc + 4]);
            }
            #pragma unroll
            for (int nt = 0; nt < 4; nt++) mma8(s[nt], qa[ks], bf[nt]);
        }
        // add bd + mask, write S to smem (own pair rows only)
        {
            int gi0 = i0 + r, gi1 = gi0 + 8;
            #pragma unroll
            for (int nt = 0; nt < 4; nt++) {
                int cbase = wc * 32 + nt * 8 + qc * 2;
                #pragma unroll
                for (int e = 0; e < 2; e++) {
                    int cc = cbase + e;
                    int gj = j0 + cc;
                    int dd0 = gj - gi0, dd1 = gj - gi1;
                    float b0 = cB[r * 68 + cc];
                    float b1 = cB[(r + 8) * 68 + cc];
                    float v0 = (dd0 >= 0 && dd0 <= 2048 && gj >= inval) ? (s[nt][e] + b0) : -1e30f;
                    float v1 = (dd1 >= 0 && dd1 <= 2048 && gj >= inval) ? (s[nt][2 + e] + b1) : -1e30f;
                    Ssm[r * 68 + cc] = v0;
                    Ssm[(r + 8) * 68 + cc] = v1;
                }
            }
        }
        asm volatile("bar.sync %0, 64;" :: "r"(barid) : "memory");

        // pair-local online softmax (4 lanes / row); P stored as tf32 bits
        {
            float* Sr = Ssm + srow * 68 + sg * 16;
            float mx = -1e30f;
            #pragma unroll
            for (int c2 = 0; c2 < 16; c2++) mx = fmaxf(mx, Sr[c2]);
            mx = fmaxf(mx, __shfl_xor_sync(0xffffffffu, mx, 1));
            mx = fmaxf(mx, __shfl_xor_sync(0xffffffffu, mx, 2));
            float mold = mrow[srow];
            float mnew = fmaxf(mold, mx);
            float sum = 0.f;
            #pragma unroll
            for (int c2 = 0; c2 < 16; c2++) {
                float p = __expf(Sr[c2] - mnew);
                ((unsigned*)Sr)[c2] = tf32cvt(p);
                sum += p;
            }
            sum += __shfl_xor_sync(0xffffffffu, sum, 1);
            sum += __shfl_xor_sync(0xffffffffu, sum, 2);
            if (sg == 0) {
                float alpha = __expf(mold - mnew);
                arow[srow] = alpha;
                lrow[srow] = lrow[srow] * alpha + sum;
                mrow[srow] = mnew;
            }
        }
        asm volatile("bar.sync %0, 64;" :: "r"(barid) : "memory");

        // phase C: rescale + O += P @ V   (V converted at fragment load)
        {
            float al0 = arow[r], al1 = arow[r + 8];
            #pragma unroll
            for (int nt = 0; nt < 8; nt++) {
                oacc[nt][0] *= al0; oacc[nt][1] *= al0;
                oacc[nt][2] *= al1; oacc[nt][3] *= al1;
            }
            const unsigned* Pu = (const unsigned*)Ssm;
            #pragma unroll
            for (int ks = 0; ks < 8; ks++) {
                const int kk = ks * 8;
                unsigned a[4], bf[8][2];
                a[0] = Pu[r * 68 + kk + qc];
                a[1] = Pu[(r + 8) * 68 + kk + qc];
                a[2] = Pu[r * 68 + kk + qc + 4];
                a[3] = Pu[(r + 8) * 68 + kk + qc + 4];
                #pragma unroll
                for (int nt = 0; nt < 8; nt++) {
                    int n = wc * 64 + nt * 8 + qr;
                    bf[nt][0] = tf32cvt(cVf[(kk + qc) * 136 + n]);
                    bf[nt][1] = tf32cvt(cVf[(kk + qc + 4) * 136 + n]);
                }
                #pragma unroll
                for (int nt = 0; nt < 8; nt++) mma8(oacc[nt], a, bf[nt]);
            }
        }
        // top-of-next-tile __syncthreads covers buffer reuse
    }

    // epilogue: normalize, round to tf32, write wv
    {
        float inv0 = 1.0f / lrow[r];
        float inv1 = 1.0f / lrow[r + 8];
        float* o0 = g_wv + ((size_t)(b * L_ + i0 + r)) * D_ + h * K_;
        float* o1 = g_wv + ((size_t)(b * L_ + i0 + r + 8)) * D_ + h * K_;
        #pragma unroll
        for (int nt = 0; nt < 8; nt++) {
            int col = wc * 64 + nt * 8 + qc * 2;
            *(float2*)(o0 + col) = make_float2(tf32rnd(oacc[nt][0] * inv0), tf32rnd(oacc[nt][1] * inv0));
            *(float2*)(o1 + col) = make_float2(tf32rnd(oacc[nt][2] * inv1), tf32rnd(oacc[nt][3] * inv1));
        }
    }
}

// ---------------- launch ----------------
extern "C" void kernel_launch(void* const* d_in, const int* in_sizes, int n_in,
                              void* d_out, int out_size)
{
    const float* x      = (const float*)d_in[0];
    const int*   pos    = (const int*)  d_in[1];
    const float* cacheK = (const float*)d_in[2];
    const float* cacheV = (const float*)d_in[3];
    const float* g_rms  = (const float*)d_in[4];
    const float* Wq     = (const float*)d_in[5];
    const float* Wk     = (const float*)d_in[6];
    const float* Wv     = (const float*)d_in[7];
    const float* Wr     = (const float*)d_in[8];
    const float* xlu    = (const float*)d_in[9];
    const float* xlv    = (const float*)d_in[10];
    const float* Wo     = (const float*)d_in[11];
    float* out          = (float*)d_out;

    cudaFuncSetAttribute(gemm_qkvr, cudaFuncAttributeMaxDynamicSharedMemorySize, GEMM_SMEM);
    cudaFuncSetAttribute(gemm_out,  cudaFuncAttributeMaxDynamicSharedMemorySize, GEMM_SMEM);
    cudaFuncSetAttribute(bd_mma,    cudaFuncAttributeMaxDynamicSharedMemorySize, BD_SMEM);
    cudaFuncSetAttribute(attn_mma,  cudaFuncAttributeMaxDynamicSharedMemorySize, ATT_SMEM);

    // 0) fused prep: weight rounding (5120 blocks) + RMSNorm (2048) + sinusoid (34)
    prep_kernel<<<7202, 256>>>(x, g_rms, Wq, Wk, Wv, Wr, Wo);

    // 1) fused Q/K/V + R projections (Q emits qu/qv directly)
    gemm_qkvr<<<dim3(D_ / 128, 17, 4), 256, GEMM_SMEM>>>(xlu, xlv);

    // 2) bd scores
    bd_mma<<<dim3(17, 4, 32), 256, BD_SMEM>>>();

    // 3) banded flash attention
    attn_mma<<<dim3(L_ / 64, B_ * H_), 256, ATT_SMEM>>>(cacheK, cacheV, pos);

    // 4) output projection
    gemm_out<<<dim3(D_ / 128, (B_ * L_) / 128), 256, GEMM_SMEM>>>(out);
}